// round 1
// baseline (speedup 1.0000x reference)
#include <cuda_runtime.h>

#define B_  8
#define C_  256
#define HW_ 128
#define NE_ 20

// ---------------- scratch (device globals: sanctioned workaround) ----------------
__device__ float g_H[(size_t)B_ * C_ * HW_ * HW_];   // 512 MB
__device__ float g_T[(size_t)B_ * C_ * HW_ * HW_];   // 512 MB
__device__ float g_pooled[B_ * C_];
__device__ float g_piror[B_ * C_];
__device__ float g_wt1[3 * C_ * 9 * C_];             // transposed res_w1: [i][c][k][o]
__device__ float g_wt2[3 * C_ * 9 * C_];             // transposed res_w2

// ---------------- f32x2 packed helpers ----------------
__device__ __forceinline__ unsigned long long pk2(float a, float b) {
    unsigned long long r;
    asm("mov.b64 %0, {%1, %2};" : "=l"(r)
        : "r"(__float_as_uint(a)), "r"(__float_as_uint(b)));
    return r;
}
__device__ __forceinline__ unsigned long long fma2(unsigned long long a,
                                                   unsigned long long b,
                                                   unsigned long long c) {
    unsigned long long d;
    asm("fma.rn.f32x2 %0, %1, %2, %3;" : "=l"(d) : "l"(a), "l"(b), "l"(c));
    return d;
}
__device__ __forceinline__ void upk2(unsigned long long v, float& x, float& y) {
    unsigned lo, hi;
    asm("mov.b64 {%0, %1}, %2;" : "=r"(lo), "=r"(hi) : "l"(v));
    x = __uint_as_float(lo);
    y = __uint_as_float(hi);
}

// ---------------- kernel 1: global average pool ----------------
__global__ void pool_kernel(const float* __restrict__ x) {
    int bc = blockIdx.x;                       // b*256 + c
    const float* p = x + (size_t)bc * (HW_ * HW_);
    float s = 0.f;
    for (int i = threadIdx.x; i < HW_ * HW_; i += 256) s += p[i];
    __shared__ float red[256];
    red[threadIdx.x] = s;
    __syncthreads();
    for (int o = 128; o > 0; o >>= 1) {
        if (threadIdx.x < o) red[threadIdx.x] += red[threadIdx.x + o];
        __syncthreads();
    }
    if (threadIdx.x == 0) g_pooled[bc] = red[0] * (1.0f / (HW_ * HW_));
}

// ---------------- kernel 2: mapping net + Gumbel quantize -> piror[b][c] ----------------
__global__ void piror_kernel(const float* __restrict__ Wmap,
                             const float* __restrict__ proj_w,
                             const float* __restrict__ proj_b,
                             const float* __restrict__ embed,
                             const float* __restrict__ gumbel_u) {
    __shared__ float m[C_];
    __shared__ float sc[NE_];
    __shared__ int sidx;
    int tid = threadIdx.x;
    for (int b = 0; b < B_; b++) {
        // m = sigmoid(W_map @ pooled)
        float acc = 0.f;
        for (int c = 0; c < C_; c++)
            acc += Wmap[tid * C_ + c] * g_pooled[b * C_ + c];
        m[tid] = 1.0f / (1.0f + expf(-acc));
        __syncthreads();
        // logits + gumbel noise
        if (tid < NE_) {
            float l = proj_b[tid];
            for (int c = 0; c < C_; c++) l += proj_w[tid * C_ + c] * m[c];
            float u = gumbel_u[b * NE_ + tid];
            float g = -logf(-logf(u + 1e-10f) + 1e-10f);
            sc[tid] = l + g;   // TAU = 1
        }
        __syncthreads();
        if (tid == 0) {
            int best = 0;
            float bv = sc[0];
            for (int n = 1; n < NE_; n++)
                if (sc[n] > bv) { bv = sc[n]; best = n; }
            sidx = best;
        }
        __syncthreads();
        g_piror[b * C_ + tid] = embed[sidx * C_ + tid];
        __syncthreads();
    }
}

// ---------------- kernel 3: h = x + piror (broadcast over HW) ----------------
__global__ void add_piror_kernel(const float* __restrict__ x) {
    size_t i = (size_t)blockIdx.x * blockDim.x + threadIdx.x;  // float4 index
    size_t total4 = (size_t)B_ * C_ * HW_ * HW_ / 4;
    if (i >= total4) return;
    int bc = (int)(i >> 12);                   // (i*4)/16384
    float p = g_piror[bc];
    float4 v = ((const float4*)x)[i];
    v.x += p; v.y += p; v.z += p; v.w += p;
    ((float4*)g_H)[i] = v;
}

// ---------------- kernel 4: weight transpose [i][o][c][k] -> [i][c][k][o] ----------------
__global__ void transpose_w_kernel(const float* __restrict__ w1,
                                   const float* __restrict__ w2) {
    size_t n = (size_t)3 * C_ * 9 * C_;
    size_t idx = (size_t)blockIdx.x * blockDim.x + threadIdx.x;
    if (idx >= n) return;
    int o = (int)(idx % C_);
    size_t t = idx / C_;
    int k = (int)(t % 9);  t /= 9;
    int c = (int)(t % C_);
    int i = (int)(t / C_);
    size_t src = ((((size_t)i * C_ + o) * C_ + c) * 9) + k;
    g_wt1[idx] = w1[src];
    g_wt2[idx] = w2[src];
}

// ---------------- conv3x3 (direct, packed f32x2) ----------------
// MODE 0: out = relu(conv(g_H, w1) + b1)           -> g_T
// MODE 1: out = g_H + conv(g_T, w2) + b2           -> g_H (in-place skip, safe per-element)
// MODE 2: same as 1 but writes d_out
template <int MODE>
__global__ void __launch_bounds__(256)
conv3x3_kernel(const float* __restrict__ bias, float* dout, int widx) {
    const float* __restrict__ in = (MODE == 0) ? g_H : g_T;
    const float* __restrict__ wt =
        ((MODE == 0) ? g_wt1 : g_wt2) + (size_t)widx * (C_ * 9 * C_);
    float* out = (MODE == 2) ? dout : ((MODE == 0) ? g_T : g_H);
    const float* skip = g_H;   // used only when MODE != 0

    __shared__ float ism[8 * 18 * 20];   // 8 ci x 18 rows x 20 (padded) cols
    __shared__ float wsm[8 * 9 * 64];    // 8 ci x 9 k x 64 oc

    const int tid  = threadIdx.x;
    const int ocg  = tid >> 5;           // 0..7 (8 oc per thread)
    const int sg   = tid & 31;
    const int trow = sg >> 1;            // 0..15
    const int tcol = (sg & 1) << 3;      // 0 or 8

    const int bx0 = (blockIdx.x & 7) << 4;
    const int by0 = (blockIdx.x >> 3) << 4;
    const int ocb = blockIdx.y << 6;
    const int b   = blockIdx.z;

    unsigned long long acc[4][8];
#pragma unroll
    for (int j = 0; j < 4; j++)
#pragma unroll
        for (int i = 0; i < 8; i++) acc[j][i] = 0ULL;

    const size_t in_b = (size_t)b * C_ * HW_ * HW_;

#pragma unroll 1
    for (int c0 = 0; c0 < C_; c0 += 8) {
        __syncthreads();
        // ---- load input tile (with halo, zero padded) ----
        for (int idx = tid; idx < 8 * 18 * 18; idx += 256) {
            int ch  = idx / 324;
            int rem = idx - ch * 324;
            int r   = rem / 18;
            int col = rem - r * 18;
            int gy = by0 + r - 1, gx = bx0 + col - 1;
            float v = 0.f;
            if ((unsigned)gy < HW_ && (unsigned)gx < HW_)
                v = in[in_b + (size_t)(c0 + ch) * (HW_ * HW_) + gy * HW_ + gx];
            ism[(ch * 18 + r) * 20 + col] = v;
        }
        // ---- load weights (coalesced from transposed layout) ----
        for (int idx = tid; idx < 8 * 9 * 64; idx += 256) {
            int ch  = idx / 576;
            int rem = idx - ch * 576;
            int k = rem >> 6;
            int o = rem & 63;
            wsm[idx] = wt[((size_t)(c0 + ch) * 9 + k) * C_ + ocb + o];
        }
        __syncthreads();

#pragma unroll 1
        for (int ch = 0; ch < 8; ch++) {
#pragma unroll
            for (int ky = 0; ky < 3; ky++) {
                const float4* rp =
                    (const float4*)&ism[(ch * 18 + trow + ky) * 20 + tcol];
                float4 a0 = rp[0], a1 = rp[1], a2 = rp[2];
                float rr[10] = {a0.x, a0.y, a0.z, a0.w,
                                a1.x, a1.y, a1.z, a1.w,
                                a2.x, a2.y};
                unsigned long long rb[10];
#pragma unroll
                for (int t = 0; t < 10; t++) rb[t] = pk2(rr[t], rr[t]);
#pragma unroll
                for (int kx = 0; kx < 3; kx++) {
                    const float4* wp =
                        (const float4*)&wsm[(ch * 9 + ky * 3 + kx) * 64 + (ocg << 3)];
                    float4 w0 = wp[0], w1 = wp[1];
                    unsigned long long wv0 = pk2(w0.x, w0.y);
                    unsigned long long wv1 = pk2(w0.z, w0.w);
                    unsigned long long wv2 = pk2(w1.x, w1.y);
                    unsigned long long wv3 = pk2(w1.z, w1.w);
#pragma unroll
                    for (int i = 0; i < 8; i++) {
                        unsigned long long bb = rb[kx + i];
                        acc[0][i] = fma2(wv0, bb, acc[0][i]);
                        acc[1][i] = fma2(wv1, bb, acc[1][i]);
                        acc[2][i] = fma2(wv2, bb, acc[2][i]);
                        acc[3][i] = fma2(wv3, bb, acc[3][i]);
                    }
                }
            }
        }
    }

    // ---- epilogue: bias (+relu | +skip), vectorized stores ----
    const int gy = by0 + trow, gx = bx0 + tcol;
#pragma unroll
    for (int j = 0; j < 4; j++) {
        float lo[8], hi[8];
#pragma unroll
        for (int i = 0; i < 8; i++) upk2(acc[j][i], lo[i], hi[i]);
#pragma unroll
        for (int h2 = 0; h2 < 2; h2++) {
            float* v = h2 ? hi : lo;
            int oc = ocb + (ocg << 3) + (j << 1) + h2;
            float bb = bias[oc];
            size_t off = in_b + (size_t)oc * (HW_ * HW_) + (size_t)gy * HW_ + gx;
            float o0[8];
#pragma unroll
            for (int i = 0; i < 8; i++) {
                float t = v[i] + bb;
                if (MODE == 0) t = fmaxf(t, 0.f);
                o0[i] = t;
            }
            if (MODE != 0) {
                float4 s0 = *(const float4*)(skip + off);
                float4 s1 = *(const float4*)(skip + off + 4);
                o0[0] += s0.x; o0[1] += s0.y; o0[2] += s0.z; o0[3] += s0.w;
                o0[4] += s1.x; o0[5] += s1.y; o0[6] += s1.z; o0[7] += s1.w;
            }
            *(float4*)(out + off)     = make_float4(o0[0], o0[1], o0[2], o0[3]);
            *(float4*)(out + off + 4) = make_float4(o0[4], o0[5], o0[6], o0[7]);
        }
    }
}

// ---------------- launcher ----------------
extern "C" void kernel_launch(void* const* d_in, const int* in_sizes, int n_in,
                              void* d_out, int out_size) {
    const float* x        = (const float*)d_in[0];
    const float* gumbel_u = (const float*)d_in[1];
    const float* W_map    = (const float*)d_in[2];
    const float* proj_w   = (const float*)d_in[3];
    const float* proj_b   = (const float*)d_in[4];
    const float* embed    = (const float*)d_in[5];
    const float* res_w1   = (const float*)d_in[6];
    const float* res_b1   = (const float*)d_in[7];
    const float* res_w2   = (const float*)d_in[8];
    const float* res_b2   = (const float*)d_in[9];
    float* out = (float*)d_out;

    // 1) pooled mean per (b,c)
    pool_kernel<<<B_ * C_, 256>>>(x);
    // 2) mapping net + gumbel argmax -> piror
    piror_kernel<<<1, 256>>>(W_map, proj_w, proj_b, embed, gumbel_u);
    // 3) h = x + piror  -> g_H
    {
        size_t total4 = (size_t)B_ * C_ * HW_ * HW_ / 4;
        add_piror_kernel<<<(unsigned)((total4 + 255) / 256), 256>>>(x);
    }
    // 4) weight transpose (both stacks)
    {
        size_t n = (size_t)3 * C_ * 9 * C_;
        transpose_w_kernel<<<(unsigned)((n + 255) / 256), 256>>>(res_w1, res_w2);
    }
    // 5) 3 residual blocks (6 convs)
    dim3 cgrid(64, 4, B_);
    for (int i = 0; i < 3; i++) {
        conv3x3_kernel<0><<<cgrid, 256>>>(res_b1 + i * C_, nullptr, i);
        if (i < 2)
            conv3x3_kernel<1><<<cgrid, 256>>>(res_b2 + i * C_, nullptr, i);
        else
            conv3x3_kernel<2><<<cgrid, 256>>>(res_b2 + i * C_, out, i);
    }
}

// round 2
// speedup vs baseline: 1.0016x; 1.0016x over previous
#include <cuda_runtime.h>

#define B_  8
#define C_  256
#define HW_ 128
#define NE_ 20

// ---------------- scratch (device globals: sanctioned workaround) ----------------
__device__ float g_H[(size_t)B_ * C_ * HW_ * HW_];   // 512 MB
__device__ float g_T[(size_t)B_ * C_ * HW_ * HW_];   // 512 MB
__device__ float g_pooled[B_ * C_];
__device__ float g_piror[B_ * C_];
__device__ float g_wt1[3 * C_ * 9 * C_];             // transposed res_w1: [i][c][k][o]
__device__ float g_wt2[3 * C_ * 9 * C_];             // transposed res_w2

// ---------------- f32x2 packed helpers ----------------
__device__ __forceinline__ unsigned long long pk2(float a, float b) {
    unsigned long long r;
    asm("mov.b64 %0, {%1, %2};" : "=l"(r)
        : "r"(__float_as_uint(a)), "r"(__float_as_uint(b)));
    return r;
}
__device__ __forceinline__ unsigned long long fma2(unsigned long long a,
                                                   unsigned long long b,
                                                   unsigned long long c) {
    unsigned long long d;
    asm("fma.rn.f32x2 %0, %1, %2, %3;" : "=l"(d) : "l"(a), "l"(b), "l"(c));
    return d;
}
__device__ __forceinline__ void upk2(unsigned long long v, float& x, float& y) {
    unsigned lo, hi;
    asm("mov.b64 {%0, %1}, %2;" : "=r"(lo), "=r"(hi) : "l"(v));
    x = __uint_as_float(lo);
    y = __uint_as_float(hi);
}

// ---------------- kernel 1: global average pool ----------------
__global__ void pool_kernel(const float* __restrict__ x) {
    int bc = blockIdx.x;                       // b*256 + c
    const float* p = x + (size_t)bc * (HW_ * HW_);
    float s = 0.f;
    for (int i = threadIdx.x; i < HW_ * HW_; i += 256) s += p[i];
    __shared__ float red[256];
    red[threadIdx.x] = s;
    __syncthreads();
    for (int o = 128; o > 0; o >>= 1) {
        if (threadIdx.x < o) red[threadIdx.x] += red[threadIdx.x + o];
        __syncthreads();
    }
    if (threadIdx.x == 0) g_pooled[bc] = red[0] * (1.0f / (HW_ * HW_));
}

// ---------------- kernel 2: mapping net + Gumbel quantize -> piror[b][c] ----------------
__global__ void piror_kernel(const float* __restrict__ Wmap,
                             const float* __restrict__ proj_w,
                             const float* __restrict__ proj_b,
                             const float* __restrict__ embed,
                             const float* __restrict__ gumbel_u) {
    __shared__ float m[C_];
    __shared__ float sc[NE_];
    __shared__ int sidx;
    int tid = threadIdx.x;
    for (int b = 0; b < B_; b++) {
        // m = sigmoid(W_map @ pooled)
        float acc = 0.f;
        for (int c = 0; c < C_; c++)
            acc += Wmap[tid * C_ + c] * g_pooled[b * C_ + c];
        m[tid] = 1.0f / (1.0f + expf(-acc));
        __syncthreads();
        // logits + gumbel noise
        if (tid < NE_) {
            float l = proj_b[tid];
            for (int c = 0; c < C_; c++) l += proj_w[tid * C_ + c] * m[c];
            float u = gumbel_u[b * NE_ + tid];
            float g = -logf(-logf(u + 1e-10f) + 1e-10f);
            sc[tid] = l + g;   // TAU = 1
        }
        __syncthreads();
        if (tid == 0) {
            int best = 0;
            float bv = sc[0];
            for (int n = 1; n < NE_; n++)
                if (sc[n] > bv) { bv = sc[n]; best = n; }
            sidx = best;
        }
        __syncthreads();
        g_piror[b * C_ + tid] = embed[sidx * C_ + tid];
        __syncthreads();
    }
}

// ---------------- kernel 3: h = x + piror (broadcast over HW) ----------------
__global__ void add_piror_kernel(const float* __restrict__ x) {
    size_t i = (size_t)blockIdx.x * blockDim.x + threadIdx.x;  // float4 index
    size_t total4 = (size_t)B_ * C_ * HW_ * HW_ / 4;
    if (i >= total4) return;
    int bc = (int)(i >> 12);                   // (i*4)/16384
    float p = g_piror[bc];
    float4 v = ((const float4*)x)[i];
    v.x += p; v.y += p; v.z += p; v.w += p;
    ((float4*)g_H)[i] = v;
}

// ---------------- kernel 4: weight transpose [i][o][c][k] -> [i][c][k][o] ----------------
__global__ void transpose_w_kernel(const float* __restrict__ w1,
                                   const float* __restrict__ w2) {
    size_t n = (size_t)3 * C_ * 9 * C_;
    size_t idx = (size_t)blockIdx.x * blockDim.x + threadIdx.x;
    if (idx >= n) return;
    int o = (int)(idx % C_);
    size_t t = idx / C_;
    int k = (int)(t % 9);  t /= 9;
    int c = (int)(t % C_);
    int i = (int)(t / C_);
    size_t src = ((((size_t)i * C_ + o) * C_ + c) * 9) + k;
    g_wt1[idx] = w1[src];
    g_wt2[idx] = w2[src];
}

// ---------------- conv3x3 (direct, packed f32x2) ----------------
// MODE 0: out = relu(conv(g_H, w1) + b1)           -> g_T
// MODE 1: out = g_H + conv(g_T, w2) + b2           -> g_H (in-place skip, safe per-element)
// MODE 2: same as 1 but writes d_out
template <int MODE>
__global__ void __launch_bounds__(256)
conv3x3_kernel(const float* __restrict__ bias, float* dout, int widx) {
    const float* __restrict__ in = (MODE == 0) ? g_H : g_T;
    const float* __restrict__ wt =
        ((MODE == 0) ? g_wt1 : g_wt2) + (size_t)widx * (C_ * 9 * C_);
    float* out = (MODE == 2) ? dout : ((MODE == 0) ? g_T : g_H);
    const float* skip = g_H;   // used only when MODE != 0

    __shared__ float ism[8 * 18 * 20];   // 8 ci x 18 rows x 20 (padded) cols
    __shared__ float wsm[8 * 9 * 64];    // 8 ci x 9 k x 64 oc

    const int tid  = threadIdx.x;
    const int ocg  = tid >> 5;           // 0..7 (8 oc per thread)
    const int sg   = tid & 31;
    const int trow = sg >> 1;            // 0..15
    const int tcol = (sg & 1) << 3;      // 0 or 8

    const int bx0 = (blockIdx.x & 7) << 4;
    const int by0 = (blockIdx.x >> 3) << 4;
    const int ocb = blockIdx.y << 6;
    const int b   = blockIdx.z;

    unsigned long long acc[4][8];
#pragma unroll
    for (int j = 0; j < 4; j++)
#pragma unroll
        for (int i = 0; i < 8; i++) acc[j][i] = 0ULL;

    const size_t in_b = (size_t)b * C_ * HW_ * HW_;

#pragma unroll 1
    for (int c0 = 0; c0 < C_; c0 += 8) {
        __syncthreads();
        // ---- load input tile (with halo, zero padded) ----
        for (int idx = tid; idx < 8 * 18 * 18; idx += 256) {
            int ch  = idx / 324;
            int rem = idx - ch * 324;
            int r   = rem / 18;
            int col = rem - r * 18;
            int gy = by0 + r - 1, gx = bx0 + col - 1;
            float v = 0.f;
            if ((unsigned)gy < HW_ && (unsigned)gx < HW_)
                v = in[in_b + (size_t)(c0 + ch) * (HW_ * HW_) + gy * HW_ + gx];
            ism[(ch * 18 + r) * 20 + col] = v;
        }
        // ---- load weights (coalesced from transposed layout) ----
        for (int idx = tid; idx < 8 * 9 * 64; idx += 256) {
            int ch  = idx / 576;
            int rem = idx - ch * 576;
            int k = rem >> 6;
            int o = rem & 63;
            wsm[idx] = wt[((size_t)(c0 + ch) * 9 + k) * C_ + ocb + o];
        }
        __syncthreads();

#pragma unroll 1
        for (int ch = 0; ch < 8; ch++) {
#pragma unroll
            for (int ky = 0; ky < 3; ky++) {
                const float4* rp =
                    (const float4*)&ism[(ch * 18 + trow + ky) * 20 + tcol];
                float4 a0 = rp[0], a1 = rp[1], a2 = rp[2];
                float rr[10] = {a0.x, a0.y, a0.z, a0.w,
                                a1.x, a1.y, a1.z, a1.w,
                                a2.x, a2.y};
                unsigned long long rb[10];
#pragma unroll
                for (int t = 0; t < 10; t++) rb[t] = pk2(rr[t], rr[t]);
#pragma unroll
                for (int kx = 0; kx < 3; kx++) {
                    const float4* wp =
                        (const float4*)&wsm[(ch * 9 + ky * 3 + kx) * 64 + (ocg << 3)];
                    float4 w0 = wp[0], w1 = wp[1];
                    unsigned long long wv0 = pk2(w0.x, w0.y);
                    unsigned long long wv1 = pk2(w0.z, w0.w);
                    unsigned long long wv2 = pk2(w1.x, w1.y);
                    unsigned long long wv3 = pk2(w1.z, w1.w);
#pragma unroll
                    for (int i = 0; i < 8; i++) {
                        unsigned long long bb = rb[kx + i];
                        acc[0][i] = fma2(wv0, bb, acc[0][i]);
                        acc[1][i] = fma2(wv1, bb, acc[1][i]);
                        acc[2][i] = fma2(wv2, bb, acc[2][i]);
                        acc[3][i] = fma2(wv3, bb, acc[3][i]);
                    }
                }
            }
        }
    }

    // ---- epilogue: bias (+relu | +skip), vectorized stores ----
    const int gy = by0 + trow, gx = bx0 + tcol;
#pragma unroll
    for (int j = 0; j < 4; j++) {
        float lo[8], hi[8];
#pragma unroll
        for (int i = 0; i < 8; i++) upk2(acc[j][i], lo[i], hi[i]);
#pragma unroll
        for (int h2 = 0; h2 < 2; h2++) {
            float* v = h2 ? hi : lo;
            int oc = ocb + (ocg << 3) + (j << 1) + h2;
            float bb = bias[oc];
            size_t off = in_b + (size_t)oc * (HW_ * HW_) + (size_t)gy * HW_ + gx;
            float o0[8];
#pragma unroll
            for (int i = 0; i < 8; i++) {
                float t = v[i] + bb;
                if (MODE == 0) t = fmaxf(t, 0.f);
                o0[i] = t;
            }
            if (MODE != 0) {
                float4 s0 = *(const float4*)(skip + off);
                float4 s1 = *(const float4*)(skip + off + 4);
                o0[0] += s0.x; o0[1] += s0.y; o0[2] += s0.z; o0[3] += s0.w;
                o0[4] += s1.x; o0[5] += s1.y; o0[6] += s1.z; o0[7] += s1.w;
            }
            *(float4*)(out + off)     = make_float4(o0[0], o0[1], o0[2], o0[3]);
            *(float4*)(out + off + 4) = make_float4(o0[4], o0[5], o0[6], o0[7]);
        }
    }
}

// ---------------- launcher ----------------
extern "C" void kernel_launch(void* const* d_in, const int* in_sizes, int n_in,
                              void* d_out, int out_size) {
    const float* x        = (const float*)d_in[0];
    const float* gumbel_u = (const float*)d_in[1];
    const float* W_map    = (const float*)d_in[2];
    const float* proj_w   = (const float*)d_in[3];
    const float* proj_b   = (const float*)d_in[4];
    const float* embed    = (const float*)d_in[5];
    const float* res_w1   = (const float*)d_in[6];
    const float* res_b1   = (const float*)d_in[7];
    const float* res_w2   = (const float*)d_in[8];
    const float* res_b2   = (const float*)d_in[9];
    float* out = (float*)d_out;

    // 1) pooled mean per (b,c)
    pool_kernel<<<B_ * C_, 256>>>(x);
    // 2) mapping net + gumbel argmax -> piror
    piror_kernel<<<1, 256>>>(W_map, proj_w, proj_b, embed, gumbel_u);
    // 3) h = x + piror  -> g_H
    {
        size_t total4 = (size_t)B_ * C_ * HW_ * HW_ / 4;
        add_piror_kernel<<<(unsigned)((total4 + 255) / 256), 256>>>(x);
    }
    // 4) weight transpose (both stacks)
    {
        size_t n = (size_t)3 * C_ * 9 * C_;
        transpose_w_kernel<<<(unsigned)((n + 255) / 256), 256>>>(res_w1, res_w2);
    }
    // 5) 3 residual blocks (6 convs)
    dim3 cgrid(64, 4, B_);
    for (int i = 0; i < 3; i++) {
        conv3x3_kernel<0><<<cgrid, 256>>>(res_b1 + i * C_, nullptr, i);
        if (i < 2)
            conv3x3_kernel<1><<<cgrid, 256>>>(res_b2 + i * C_, nullptr, i);
        else
            conv3x3_kernel<2><<<cgrid, 256>>>(res_b2 + i * C_, out, i);
    }
}

// round 3
// speedup vs baseline: 1.0019x; 1.0004x over previous
#include <cuda_runtime.h>

#define B_  8
#define C_  256
#define HW_ 128
#define NE_ 20

// ---------------- scratch (device globals: sanctioned workaround) ----------------
__device__ float g_H[(size_t)B_ * C_ * HW_ * HW_];   // 512 MB
__device__ float g_T[(size_t)B_ * C_ * HW_ * HW_];   // 512 MB
__device__ float g_pooled[B_ * C_];
__device__ float g_piror[B_ * C_];
__device__ float g_wt1[3 * C_ * 9 * C_];             // transposed res_w1: [i][c][k][o]
__device__ float g_wt2[3 * C_ * 9 * C_];             // transposed res_w2

// ---------------- f32x2 packed helpers ----------------
__device__ __forceinline__ unsigned long long pk2(float a, float b) {
    unsigned long long r;
    asm("mov.b64 %0, {%1, %2};" : "=l"(r)
        : "r"(__float_as_uint(a)), "r"(__float_as_uint(b)));
    return r;
}
__device__ __forceinline__ unsigned long long fma2(unsigned long long a,
                                                   unsigned long long b,
                                                   unsigned long long c) {
    unsigned long long d;
    asm("fma.rn.f32x2 %0, %1, %2, %3;" : "=l"(d) : "l"(a), "l"(b), "l"(c));
    return d;
}
__device__ __forceinline__ void upk2(unsigned long long v, float& x, float& y) {
    unsigned lo, hi;
    asm("mov.b64 {%0, %1}, %2;" : "=r"(lo), "=r"(hi) : "l"(v));
    x = __uint_as_float(lo);
    y = __uint_as_float(hi);
}

// ---------------- kernel 1: global average pool ----------------
__global__ void pool_kernel(const float* __restrict__ x) {
    int bc = blockIdx.x;                       // b*256 + c
    const float* p = x + (size_t)bc * (HW_ * HW_);
    float s = 0.f;
    for (int i = threadIdx.x; i < HW_ * HW_; i += 256) s += p[i];
    __shared__ float red[256];
    red[threadIdx.x] = s;
    __syncthreads();
    for (int o = 128; o > 0; o >>= 1) {
        if (threadIdx.x < o) red[threadIdx.x] += red[threadIdx.x + o];
        __syncthreads();
    }
    if (threadIdx.x == 0) g_pooled[bc] = red[0] * (1.0f / (HW_ * HW_));
}

// ---------------- kernel 2: mapping net + Gumbel quantize -> piror[b][c] ----------------
__global__ void piror_kernel(const float* __restrict__ Wmap,
                             const float* __restrict__ proj_w,
                             const float* __restrict__ proj_b,
                             const float* __restrict__ embed,
                             const float* __restrict__ gumbel_u) {
    __shared__ float m[C_];
    __shared__ float sc[NE_];
    __shared__ int sidx;
    int tid = threadIdx.x;
    for (int b = 0; b < B_; b++) {
        // m = sigmoid(W_map @ pooled)
        float acc = 0.f;
        for (int c = 0; c < C_; c++)
            acc += Wmap[tid * C_ + c] * g_pooled[b * C_ + c];
        m[tid] = 1.0f / (1.0f + expf(-acc));
        __syncthreads();
        // logits + gumbel noise
        if (tid < NE_) {
            float l = proj_b[tid];
            for (int c = 0; c < C_; c++) l += proj_w[tid * C_ + c] * m[c];
            float u = gumbel_u[b * NE_ + tid];
            float g = -logf(-logf(u + 1e-10f) + 1e-10f);
            sc[tid] = l + g;   // TAU = 1
        }
        __syncthreads();
        if (tid == 0) {
            int best = 0;
            float bv = sc[0];
            for (int n = 1; n < NE_; n++)
                if (sc[n] > bv) { bv = sc[n]; best = n; }
            sidx = best;
        }
        __syncthreads();
        g_piror[b * C_ + tid] = embed[sidx * C_ + tid];
        __syncthreads();
    }
}

// ---------------- kernel 3: h = x + piror (broadcast over HW) ----------------
__global__ void add_piror_kernel(const float* __restrict__ x) {
    size_t i = (size_t)blockIdx.x * blockDim.x + threadIdx.x;  // float4 index
    size_t total4 = (size_t)B_ * C_ * HW_ * HW_ / 4;
    if (i >= total4) return;
    int bc = (int)(i >> 12);                   // (i*4)/16384
    float p = g_piror[bc];
    float4 v = ((const float4*)x)[i];
    v.x += p; v.y += p; v.z += p; v.w += p;
    ((float4*)g_H)[i] = v;
}

// ---------------- kernel 4: weight transpose [i][o][c][k] -> [i][c][k][o] ----------------
__global__ void transpose_w_kernel(const float* __restrict__ w1,
                                   const float* __restrict__ w2) {
    size_t n = (size_t)3 * C_ * 9 * C_;
    size_t idx = (size_t)blockIdx.x * blockDim.x + threadIdx.x;
    if (idx >= n) return;
    int o = (int)(idx % C_);
    size_t t = idx / C_;
    int k = (int)(t % 9);  t /= 9;
    int c = (int)(t % C_);
    int i = (int)(t / C_);
    size_t src = ((((size_t)i * C_ + o) * C_ + c) * 9) + k;
    g_wt1[idx] = w1[src];
    g_wt2[idx] = w2[src];
}

// ---------------- conv3x3 (direct, packed f32x2) ----------------
// MODE 0: out = relu(conv(g_H, w1) + b1)           -> g_T
// MODE 1: out = g_H + conv(g_T, w2) + b2           -> g_H (in-place skip, safe per-element)
// MODE 2: same as 1 but writes d_out
template <int MODE>
__global__ void __launch_bounds__(256)
conv3x3_kernel(const float* __restrict__ bias, float* dout, int widx) {
    const float* __restrict__ in = (MODE == 0) ? g_H : g_T;
    const float* __restrict__ wt =
        ((MODE == 0) ? g_wt1 : g_wt2) + (size_t)widx * (C_ * 9 * C_);
    float* out = (MODE == 2) ? dout : ((MODE == 0) ? g_T : g_H);
    const float* skip = g_H;   // used only when MODE != 0

    __shared__ float ism[8 * 18 * 20];   // 8 ci x 18 rows x 20 (padded) cols
    __shared__ float wsm[8 * 9 * 64];    // 8 ci x 9 k x 64 oc

    const int tid  = threadIdx.x;
    const int ocg  = tid >> 5;           // 0..7 (8 oc per thread)
    const int sg   = tid & 31;
    const int trow = sg >> 1;            // 0..15
    const int tcol = (sg & 1) << 3;      // 0 or 8

    const int bx0 = (blockIdx.x & 7) << 4;
    const int by0 = (blockIdx.x >> 3) << 4;
    const int ocb = blockIdx.y << 6;
    const int b   = blockIdx.z;

    unsigned long long acc[4][8];
#pragma unroll
    for (int j = 0; j < 4; j++)
#pragma unroll
        for (int i = 0; i < 8; i++) acc[j][i] = 0ULL;

    const size_t in_b = (size_t)b * C_ * HW_ * HW_;

#pragma unroll 1
    for (int c0 = 0; c0 < C_; c0 += 8) {
        __syncthreads();
        // ---- load input tile (with halo, zero padded) ----
        for (int idx = tid; idx < 8 * 18 * 18; idx += 256) {
            int ch  = idx / 324;
            int rem = idx - ch * 324;
            int r   = rem / 18;
            int col = rem - r * 18;
            int gy = by0 + r - 1, gx = bx0 + col - 1;
            float v = 0.f;
            if ((unsigned)gy < HW_ && (unsigned)gx < HW_)
                v = in[in_b + (size_t)(c0 + ch) * (HW_ * HW_) + gy * HW_ + gx];
            ism[(ch * 18 + r) * 20 + col] = v;
        }
        // ---- load weights (coalesced from transposed layout) ----
        for (int idx = tid; idx < 8 * 9 * 64; idx += 256) {
            int ch  = idx / 576;
            int rem = idx - ch * 576;
            int k = rem >> 6;
            int o = rem & 63;
            wsm[idx] = wt[((size_t)(c0 + ch) * 9 + k) * C_ + ocb + o];
        }
        __syncthreads();

#pragma unroll 1
        for (int ch = 0; ch < 8; ch++) {
#pragma unroll
            for (int ky = 0; ky < 3; ky++) {
                const float4* rp =
                    (const float4*)&ism[(ch * 18 + trow + ky) * 20 + tcol];
                float4 a0 = rp[0], a1 = rp[1], a2 = rp[2];
                float rr[10] = {a0.x, a0.y, a0.z, a0.w,
                                a1.x, a1.y, a1.z, a1.w,
                                a2.x, a2.y};
                unsigned long long rb[10];
#pragma unroll
                for (int t = 0; t < 10; t++) rb[t] = pk2(rr[t], rr[t]);
#pragma unroll
                for (int kx = 0; kx < 3; kx++) {
                    const float4* wp =
                        (const float4*)&wsm[(ch * 9 + ky * 3 + kx) * 64 + (ocg << 3)];
                    float4 w0 = wp[0], w1 = wp[1];
                    unsigned long long wv0 = pk2(w0.x, w0.y);
                    unsigned long long wv1 = pk2(w0.z, w0.w);
                    unsigned long long wv2 = pk2(w1.x, w1.y);
                    unsigned long long wv3 = pk2(w1.z, w1.w);
#pragma unroll
                    for (int i = 0; i < 8; i++) {
                        unsigned long long bb = rb[kx + i];
                        acc[0][i] = fma2(wv0, bb, acc[0][i]);
                        acc[1][i] = fma2(wv1, bb, acc[1][i]);
                        acc[2][i] = fma2(wv2, bb, acc[2][i]);
                        acc[3][i] = fma2(wv3, bb, acc[3][i]);
                    }
                }
            }
        }
    }

    // ---- epilogue: bias (+relu | +skip), vectorized stores ----
    const int gy = by0 + trow, gx = bx0 + tcol;
#pragma unroll
    for (int j = 0; j < 4; j++) {
        float lo[8], hi[8];
#pragma unroll
        for (int i = 0; i < 8; i++) upk2(acc[j][i], lo[i], hi[i]);
#pragma unroll
        for (int h2 = 0; h2 < 2; h2++) {
            float* v = h2 ? hi : lo;
            int oc = ocb + (ocg << 3) + (j << 1) + h2;
            float bb = bias[oc];
            size_t off = in_b + (size_t)oc * (HW_ * HW_) + (size_t)gy * HW_ + gx;
            float o0[8];
#pragma unroll
            for (int i = 0; i < 8; i++) {
                float t = v[i] + bb;
                if (MODE == 0) t = fmaxf(t, 0.f);
                o0[i] = t;
            }
            if (MODE != 0) {
                float4 s0 = *(const float4*)(skip + off);
                float4 s1 = *(const float4*)(skip + off + 4);
                o0[0] += s0.x; o0[1] += s0.y; o0[2] += s0.z; o0[3] += s0.w;
                o0[4] += s1.x; o0[5] += s1.y; o0[6] += s1.z; o0[7] += s1.w;
            }
            *(float4*)(out + off)     = make_float4(o0[0], o0[1], o0[2], o0[3]);
            *(float4*)(out + off + 4) = make_float4(o0[4], o0[5], o0[6], o0[7]);
        }
    }
}

// ---------------- launcher ----------------
extern "C" void kernel_launch(void* const* d_in, const int* in_sizes, int n_in,
                              void* d_out, int out_size) {
    const float* x        = (const float*)d_in[0];
    const float* gumbel_u = (const float*)d_in[1];
    const float* W_map    = (const float*)d_in[2];
    const float* proj_w   = (const float*)d_in[3];
    const float* proj_b   = (const float*)d_in[4];
    const float* embed    = (const float*)d_in[5];
    const float* res_w1   = (const float*)d_in[6];
    const float* res_b1   = (const float*)d_in[7];
    const float* res_w2   = (const float*)d_in[8];
    const float* res_b2   = (const float*)d_in[9];
    float* out = (float*)d_out;

    // 1) pooled mean per (b,c)
    pool_kernel<<<B_ * C_, 256>>>(x);
    // 2) mapping net + gumbel argmax -> piror
    piror_kernel<<<1, 256>>>(W_map, proj_w, proj_b, embed, gumbel_u);
    // 3) h = x + piror  -> g_H
    {
        size_t total4 = (size_t)B_ * C_ * HW_ * HW_ / 4;
        add_piror_kernel<<<(unsigned)((total4 + 255) / 256), 256>>>(x);
    }
    // 4) weight transpose (both stacks)
    {
        size_t n = (size_t)3 * C_ * 9 * C_;
        transpose_w_kernel<<<(unsigned)((n + 255) / 256), 256>>>(res_w1, res_w2);
    }
    // 5) 3 residual blocks (6 convs)
    dim3 cgrid(64, 4, B_);
    for (int i = 0; i < 3; i++) {
        conv3x3_kernel<0><<<cgrid, 256>>>(res_b1 + i * C_, nullptr, i);
        if (i < 2)
            conv3x3_kernel<1><<<cgrid, 256>>>(res_b2 + i * C_, nullptr, i);
        else
            conv3x3_kernel<2><<<cgrid, 256>>>(res_b2 + i * C_, out, i);
    }
}

// round 6
// speedup vs baseline: 2.7786x; 2.7733x over previous
#include <cuda_runtime.h>
#include <cuda_bf16.h>
#include <cstdint>

#define B_  8
#define C_  256
#define HW_ 128
#define NE_ 20

typedef __nv_bfloat16 bf16;

// ---------------- device-global scratch (sanctioned; no runtime allocs) ----------------
__device__ float g_pooled[B_ * C_];
__device__ float g_piror[B_ * C_];
__device__ __align__(1024) float g_skip[(size_t)B_ * HW_ * HW_ * C_];   // NHWC fp32
// packed activations: per pixel 512 bf16 = 8 ic-chunks x [hi32 | lo32]
__device__ __align__(1024) bf16 g_actA[(size_t)B_ * HW_ * HW_ * 512];
__device__ __align__(1024) bf16 g_actB[(size_t)B_ * HW_ * HW_ * 512];
// packed weights: [i*9+ky*3+kx][oc 256][chunk 8][hi32|lo32]
__device__ __align__(1024) bf16 g_w1p[(size_t)27 * 256 * 8 * 64];
__device__ __align__(1024) bf16 g_w2p[(size_t)27 * 256 * 8 * 64];

// ---------------- PTX helpers ----------------
__device__ __forceinline__ uint32_t smem_u32(const void* p) {
    uint32_t a;
    asm("{ .reg .u64 t; cvta.to.shared.u64 t, %1; cvt.u32.u64 %0, t; }" : "=r"(a) : "l"(p));
    return a;
}
__device__ __forceinline__ void cp16(uint32_t dst, const void* src) {
    asm volatile("cp.async.cg.shared.global [%0], [%1], 16;" :: "r"(dst), "l"(src));
}
__device__ __forceinline__ void ldsm4(uint32_t* r, uint32_t a) {
    asm volatile("ldmatrix.sync.aligned.m8n8.x4.shared.b16 {%0,%1,%2,%3}, [%4];"
                 : "=r"(r[0]), "=r"(r[1]), "=r"(r[2]), "=r"(r[3]) : "r"(a));
}
__device__ __forceinline__ void mma16816(float* c, const uint32_t* a, uint32_t b0, uint32_t b1) {
    asm volatile(
        "mma.sync.aligned.m16n8k16.row.col.f32.bf16.bf16.f32 "
        "{%0,%1,%2,%3}, {%4,%5,%6,%7}, {%8,%9}, {%0,%1,%2,%3};"
        : "+f"(c[0]), "+f"(c[1]), "+f"(c[2]), "+f"(c[3])
        : "r"(a[0]), "r"(a[1]), "r"(a[2]), "r"(a[3]), "r"(b0), "r"(b1));
}

// ---------------- small kernels ----------------
__global__ void pool_kernel(const float* __restrict__ x) {
    int bc = blockIdx.x;
    const float* p = x + (size_t)bc * (HW_ * HW_);
    float s = 0.f;
    for (int i = threadIdx.x; i < HW_ * HW_; i += 256) s += p[i];
    __shared__ float red[256];
    red[threadIdx.x] = s;
    __syncthreads();
    for (int o = 128; o > 0; o >>= 1) {
        if (threadIdx.x < o) red[threadIdx.x] += red[threadIdx.x + o];
        __syncthreads();
    }
    if (threadIdx.x == 0) g_pooled[bc] = red[0] * (1.0f / (HW_ * HW_));
}

__global__ void piror_kernel(const float* __restrict__ Wmap,
                             const float* __restrict__ proj_w,
                             const float* __restrict__ proj_b,
                             const float* __restrict__ embed,
                             const float* __restrict__ gumbel_u) {
    __shared__ float m[C_];
    __shared__ float sc[NE_];
    __shared__ int sidx;
    int tid = threadIdx.x;
    for (int b = 0; b < B_; b++) {
        float acc = 0.f;
        for (int c = 0; c < C_; c++)
            acc += Wmap[tid * C_ + c] * g_pooled[b * C_ + c];
        m[tid] = 1.0f / (1.0f + expf(-acc));
        __syncthreads();
        if (tid < NE_) {
            float l = proj_b[tid];
            for (int c = 0; c < C_; c++) l += proj_w[tid * C_ + c] * m[c];
            float u = gumbel_u[b * NE_ + tid];
            float g = -logf(-logf(u + 1e-10f) + 1e-10f);
            sc[tid] = l + g;
        }
        __syncthreads();
        if (tid == 0) {
            int best = 0;
            float bv = sc[0];
            for (int n = 1; n < NE_; n++)
                if (sc[n] > bv) { bv = sc[n]; best = n; }
            sidx = best;
        }
        __syncthreads();
        g_piror[b * C_ + tid] = embed[sidx * C_ + tid];
        __syncthreads();
    }
}

// NCHW fp32 + piror -> {skip NHWC fp32, packed bf16 hi/lo activations}
__global__ void input_prep(const float* __restrict__ x) {
    __shared__ float tile[32][33];
    int tx = threadIdx.x, ty = threadIdx.y;          // 32 x 8
    int by = blockIdx.x;                             // b*128 + y
    int b = by >> 7, y = by & 127;
    int x0 = blockIdx.y * 32, c0 = blockIdx.z * 32;
#pragma unroll
    for (int i = 0; i < 4; i++) {
        int cl = ty * 4 + i;
        tile[cl][tx] = x[((size_t)(b * C_ + c0 + cl) * HW_ + y) * HW_ + x0 + tx];
    }
    __syncthreads();
#pragma unroll
    for (int i = 0; i < 4; i++) {
        int xl = ty * 4 + i;
        int c = c0 + tx;
        float v = tile[tx][xl] + g_piror[b * C_ + c];
        size_t pix = (size_t)(b * HW_ + y) * HW_ + x0 + xl;
        g_skip[pix * 256 + c] = v;
        bf16 h = __float2bfloat16(v);
        size_t d = pix * 512 + ((size_t)(c >> 5) << 6) + (c & 31);
        g_actA[d] = h;
        g_actA[d + 32] = __float2bfloat16(v - __bfloat162float(h));
    }
}

// [i][oc][ic][ky][kx] fp32 -> packed [tap27][oc][chunk][hi32|lo32], both stacks
__global__ void weight_prep(const float* __restrict__ w1, const float* __restrict__ w2) {
    int idx = blockIdx.x * 256 + threadIdx.x;        // < 27*256*256
    int ic = idx & 255, oc = (idx >> 8) & 255, t9 = idx >> 16;
    int i = t9 / 9, tap = t9 - 9 * i;
    size_t src = (((size_t)(i * C_ + oc) * C_ + ic) * 9) + tap;
    size_t d = (((size_t)t9 * 256 + oc) * 8 + (ic >> 5)) * 64 + (ic & 31);
    float a = w1[src];
    bf16 ah = __float2bfloat16(a);
    g_w1p[d] = ah;
    g_w1p[d + 32] = __float2bfloat16(a - __bfloat162float(ah));
    float c = w2[src];
    bf16 ch = __float2bfloat16(c);
    g_w2p[d] = ch;
    g_w2p[d + 32] = __float2bfloat16(c - __bfloat162float(ch));
}

__device__ __forceinline__ void store_pair_packed(bf16* base, size_t pix, int oc,
                                                  float v0, float v1) {
    size_t o = pix * 512 + ((size_t)(oc >> 5) << 6) + (oc & 31);
    bf16 h0 = __float2bfloat16(v0), h1 = __float2bfloat16(v1);
    *(__nv_bfloat162*)(base + o) = __halves2bfloat162(h0, h1);
    bf16 l0 = __float2bfloat16(v0 - __bfloat162float(h0));
    bf16 l1 = __float2bfloat16(v1 - __bfloat162float(h1));
    *(__nv_bfloat162*)(base + o + 32) = __halves2bfloat162(l0, l1);
}

// ---------------- conv3x3 on classic HMMA (mma.sync bf16, split-K precision) ----------------
// MODE 0: relu(conv(g_actA, w1)+b1) -> g_actB
// MODE 1: g_skip += conv(g_actB, w2)+b2; also -> g_actA
// MODE 2: like 1 but writes NCHW d_out
#define A_BYTES (130 * 128)
#define W_BYTES (384 * 128)
#define STG     (A_BYTES + W_BYTES)      // 65792
#define SMEMSZ  (2 * STG)                // 131584

template <int MODE>
__global__ void __launch_bounds__(256, 1)
conv_hmma(const float* __restrict__ bias, float* __restrict__ dout, int widx) {
    extern __shared__ char sm[];
    const uint32_t sb = smem_u32(sm);
    const int tid = threadIdx.x, lane = tid & 31, wid = tid >> 5;
    const int y = blockIdx.x, ocb = blockIdx.y, b = blockIdx.z;

    const char* __restrict__ actb = (const char*)((MODE == 0) ? g_actA : g_actB);
    const char* __restrict__ wpb  = (const char*)((MODE == 0) ? g_w1p : g_w2p);

    // zero the two x-halo rows (px_mem 0 and 129) of both buffers; never overwritten
    if (tid < 32) {
        int bufi = tid >> 4, rr = (tid >> 3) & 1, seg = tid & 7;
        uint32_t addr = sb + bufi * STG + (rr ? 129 : 0) * 128 + seg * 16;
        asm volatile("st.shared.v4.b32 [%0], {%1,%1,%1,%1};" :: "r"(addr), "r"(0) : "memory");
    }

    int kys[3];
    int nky = 0;
#pragma unroll
    for (int ky = 0; ky < 3; ky++) {
        int yin = y + ky - 1;
        if (yin >= 0 && yin < HW_) kys[nky++] = ky;
    }
    const int S = nky * 8;

    auto load_stage = [&](int s, int buf) {
        int ky = kys[s >> 3], c = s & 7;
        int yin = y + ky - 1;
        size_t aSrc = (size_t)(b * HW_ + yin) * HW_ * 1024 + (size_t)c * 128;
        uint32_t bb = sb + buf * STG;
        int t9 = widx * 9 + ky * 3;
#pragma unroll
        for (int j = 0; j < 16; j++) {
            int id = j * 256 + tid;
            if (id < 1024) {
                int px = id >> 3, seg = id & 7;
                const char* src = actb + aSrc + (size_t)px * 1024 + seg * 16;
                uint32_t dst = bb + (px + 1) * 128 + ((seg * 16) ^ (((px + 1) & 7) << 4));
                cp16(dst, src);
            } else {
                int w = id - 1024;
                int row = w >> 3, seg = w & 7;
                int kx = row >> 7, ocl = row & 127;
                const char* src = wpb +
                    ((((size_t)(t9 + kx) * 256 + ocb * 128 + ocl) * 8 + c) << 7) + seg * 16;
                uint32_t dst = bb + A_BYTES + row * 128 + ((seg * 16) ^ ((row & 7) << 4));
                cp16(dst, src);
            }
        }
        asm volatile("cp.async.commit_group;" ::: "memory");
    };

    // per-warp fragment geometry
    const int m0 = (wid >> 1) * 32;          // px tile base
    const int wn = (wid & 1) * 64;           // oc tile base (local)
    const int aRow0 = m0 + (lane & 15);
    const int aCol = (lane >> 4) * 16;
    const int wRowL = wn + ((lane >> 4) << 3) + (lane & 7);
    const int wKsel = ((lane >> 3) & 1) * 16;
    const uint32_t wSw = (uint32_t)((lane & 7) << 4);

    float acc[2][8][4];
#pragma unroll
    for (int mt = 0; mt < 2; mt++)
#pragma unroll
        for (int g = 0; g < 8; g++)
#pragma unroll
            for (int k = 0; k < 4; k++) acc[mt][g][k] = 0.f;

    auto mma_stage = [&](uint32_t base) {
        uint32_t aB = base, wB = base + A_BYTES;
#pragma unroll
        for (int kx = 0; kx < 3; kx++) {
            int prow = aRow0 + kx;
            uint32_t aRowAddr = aB + prow * 128;
            uint32_t aSw = (uint32_t)((prow & 7) << 4);
            uint32_t wRowAddr = wB + (kx * 128 + wRowL) * 128;
#pragma unroll
            for (int kh = 0; kh < 2; kh++) {
                int k0b = kh * 32;
                uint32_t ah[2][4], al[2][4], bw[4][4];
                uint32_t aH = aRowAddr + (uint32_t)((k0b + aCol) ^ aSw);
                ldsm4(ah[0], aH);
                ldsm4(ah[1], aH + 16 * 128);
                uint32_t aL = aRowAddr + (uint32_t)((64 + k0b + aCol) ^ aSw);
                ldsm4(al[0], aL);
                ldsm4(al[1], aL + 16 * 128);
                uint32_t wH = wRowAddr + (uint32_t)((k0b + wKsel) ^ wSw);
#pragma unroll
                for (int bt = 0; bt < 4; bt++) ldsm4(bw[bt], wH + bt * 16 * 128);
#pragma unroll
                for (int mt = 0; mt < 2; mt++)
#pragma unroll
                    for (int g = 0; g < 8; g++)
                        mma16816(acc[mt][g], ah[mt], bw[g >> 1][(g & 1) * 2],
                                 bw[g >> 1][(g & 1) * 2 + 1]);
#pragma unroll
                for (int mt = 0; mt < 2; mt++)
#pragma unroll
                    for (int g = 0; g < 8; g++)
                        mma16816(acc[mt][g], al[mt], bw[g >> 1][(g & 1) * 2],
                                 bw[g >> 1][(g & 1) * 2 + 1]);
                uint32_t wL = wRowAddr + (uint32_t)((64 + k0b + wKsel) ^ wSw);
#pragma unroll
                for (int bt = 0; bt < 4; bt++) ldsm4(bw[bt], wL + bt * 16 * 128);
#pragma unroll
                for (int mt = 0; mt < 2; mt++)
#pragma unroll
                    for (int g = 0; g < 8; g++)
                        mma16816(acc[mt][g], ah[mt], bw[g >> 1][(g & 1) * 2],
                                 bw[g >> 1][(g & 1) * 2 + 1]);
            }
        }
    };

    load_stage(0, 0);
#pragma unroll 1
    for (int s = 0; s < S; s++) {
        if (s + 1 < S) {
            load_stage(s + 1, (s + 1) & 1);
            asm volatile("cp.async.wait_group 1;" ::: "memory");
        } else {
            asm volatile("cp.async.wait_group 0;" ::: "memory");
        }
        __syncthreads();
        mma_stage(sb + (uint32_t)(s & 1) * STG);
        __syncthreads();
    }

    // ---- epilogue ----
    const int r = lane >> 2, q = lane & 3;
    const int ocbase = ocb * 128 + wn;
    const size_t pixBase = (size_t)(b * HW_ + y) * HW_;
#pragma unroll
    for (int mt = 0; mt < 2; mt++) {
        int px0 = m0 + mt * 16 + r;
#pragma unroll
        for (int g = 0; g < 8; g++) {
            int oc = ocbase + g * 8 + 2 * q;
            float bz0 = __ldg(&bias[oc]), bz1 = __ldg(&bias[oc + 1]);
#pragma unroll
            for (int hh = 0; hh < 2; hh++) {
                int px = px0 + hh * 8;
                float v0 = acc[mt][g][hh * 2 + 0] + bz0;
                float v1 = acc[mt][g][hh * 2 + 1] + bz1;
                size_t pix = pixBase + px;
                if (MODE == 0) {
                    v0 = fmaxf(v0, 0.f);
                    v1 = fmaxf(v1, 0.f);
                    store_pair_packed(g_actB, pix, oc, v0, v1);
                } else {
                    float2 sk = *(const float2*)&g_skip[pix * 256 + oc];
                    v0 += sk.x;
                    v1 += sk.y;
                    if (MODE == 1) {
                        *(float2*)&g_skip[pix * 256 + oc] = make_float2(v0, v1);
                        store_pair_packed(g_actA, pix, oc, v0, v1);
                    } else {
                        dout[((size_t)(b * C_ + oc) * HW_ + y) * HW_ + px] = v0;
                        dout[((size_t)(b * C_ + oc + 1) * HW_ + y) * HW_ + px] = v1;
                    }
                }
            }
        }
    }
}

// ---------------- launcher ----------------
extern "C" void kernel_launch(void* const* d_in, const int* in_sizes, int n_in,
                              void* d_out, int out_size) {
    const float* x        = (const float*)d_in[0];
    const float* gumbel_u = (const float*)d_in[1];
    const float* W_map    = (const float*)d_in[2];
    const float* proj_w   = (const float*)d_in[3];
    const float* proj_b   = (const float*)d_in[4];
    const float* embed    = (const float*)d_in[5];
    const float* res_w1   = (const float*)d_in[6];
    const float* res_b1   = (const float*)d_in[7];
    const float* res_w2   = (const float*)d_in[8];
    const float* res_b2   = (const float*)d_in[9];
    float* out = (float*)d_out;

    cudaFuncSetAttribute(conv_hmma<0>, cudaFuncAttributeMaxDynamicSharedMemorySize, SMEMSZ);
    cudaFuncSetAttribute(conv_hmma<1>, cudaFuncAttributeMaxDynamicSharedMemorySize, SMEMSZ);
    cudaFuncSetAttribute(conv_hmma<2>, cudaFuncAttributeMaxDynamicSharedMemorySize, SMEMSZ);

    pool_kernel<<<B_ * C_, 256>>>(x);
    piror_kernel<<<1, 256>>>(W_map, proj_w, proj_b, embed, gumbel_u);
    input_prep<<<dim3(B_ * HW_, 4, 8), dim3(32, 8)>>>(x);
    weight_prep<<<(27 * 256 * 256) / 256, 256>>>(res_w1, res_w2);

    dim3 cg(HW_, 2, B_);
    for (int i = 0; i < 3; i++) {
        conv_hmma<0><<<cg, 256, SMEMSZ>>>(res_b1 + i * C_, nullptr, i);
        if (i < 2)
            conv_hmma<1><<<cg, 256, SMEMSZ>>>(res_b2 + i * C_, nullptr, i);
        else
            conv_hmma<2><<<cg, 256, SMEMSZ>>>(res_b2 + i * C_, out, i);
    }
}

// round 8
// speedup vs baseline: 3.9373x; 1.4170x over previous
#include <cuda_runtime.h>
#include <cuda_fp16.h>
#include <cstdint>

#define B_  8
#define C_  256
#define HW_ 128
#define NE_ 20

// ---------------- device-global scratch (sanctioned; no runtime allocs) ----------------
__device__ float g_pooled[B_ * C_];
__device__ float g_piror[B_ * C_];
__device__ __align__(1024) float g_skip[(size_t)B_ * HW_ * HW_ * C_];   // NHWC fp32
// packed activations: per pixel 512 halves = [hi 256 ic][lo 256 ic]
__device__ __align__(1024) __half g_actA[(size_t)B_ * HW_ * HW_ * 512];
__device__ __align__(1024) __half g_actB[(size_t)B_ * HW_ * HW_ * 512];
// packed weights (single fp16): [i*9+ky*3+kx][oc 256][ic 256]
__device__ __align__(1024) __half g_w1p[(size_t)27 * 256 * 256];
__device__ __align__(1024) __half g_w2p[(size_t)27 * 256 * 256];

// ---------------- PTX helpers ----------------
__device__ __forceinline__ uint32_t smem_u32(const void* p) {
    uint32_t a;
    asm("{ .reg .u64 t; cvta.to.shared.u64 t, %1; cvt.u32.u64 %0, t; }" : "=r"(a) : "l"(p));
    return a;
}
__device__ __forceinline__ void cp16(uint32_t dst, const void* src) {
    asm volatile("cp.async.cg.shared.global [%0], [%1], 16;" :: "r"(dst), "l"(src));
}
__device__ __forceinline__ void ldsm4(uint32_t* r, uint32_t a) {
    asm volatile("ldmatrix.sync.aligned.m8n8.x4.shared.b16 {%0,%1,%2,%3}, [%4];"
                 : "=r"(r[0]), "=r"(r[1]), "=r"(r[2]), "=r"(r[3]) : "r"(a));
}
__device__ __forceinline__ void mma16816(float* c, const uint32_t* a, uint32_t b0, uint32_t b1) {
    asm volatile(
        "mma.sync.aligned.m16n8k16.row.col.f32.f16.f16.f32 "
        "{%0,%1,%2,%3}, {%4,%5,%6,%7}, {%8,%9}, {%0,%1,%2,%3};"
        : "+f"(c[0]), "+f"(c[1]), "+f"(c[2]), "+f"(c[3])
        : "r"(a[0]), "r"(a[1]), "r"(a[2]), "r"(a[3]), "r"(b0), "r"(b1));
}

// ---------------- small kernels ----------------
__global__ void pool_kernel(const float* __restrict__ x) {
    int bc = blockIdx.x;
    const float* p = x + (size_t)bc * (HW_ * HW_);
    float s = 0.f;
    for (int i = threadIdx.x; i < HW_ * HW_; i += 256) s += p[i];
    __shared__ float red[256];
    red[threadIdx.x] = s;
    __syncthreads();
    for (int o = 128; o > 0; o >>= 1) {
        if (threadIdx.x < o) red[threadIdx.x] += red[threadIdx.x + o];
        __syncthreads();
    }
    if (threadIdx.x == 0) g_pooled[bc] = red[0] * (1.0f / (HW_ * HW_));
}

__global__ void piror_kernel(const float* __restrict__ Wmap,
                             const float* __restrict__ proj_w,
                             const float* __restrict__ proj_b,
                             const float* __restrict__ embed,
                             const float* __restrict__ gumbel_u) {
    __shared__ float m[C_];
    __shared__ float sc[NE_];
    __shared__ int sidx;
    int tid = threadIdx.x;
    for (int b = 0; b < B_; b++) {
        float acc = 0.f;
        for (int c = 0; c < C_; c++)
            acc += Wmap[tid * C_ + c] * g_pooled[b * C_ + c];
        m[tid] = 1.0f / (1.0f + expf(-acc));
        __syncthreads();
        if (tid < NE_) {
            float l = proj_b[tid];
            for (int c = 0; c < C_; c++) l += proj_w[tid * C_ + c] * m[c];
            float u = gumbel_u[b * NE_ + tid];
            float g = -logf(-logf(u + 1e-10f) + 1e-10f);
            sc[tid] = l + g;
        }
        __syncthreads();
        if (tid == 0) {
            int best = 0;
            float bv = sc[0];
            for (int n = 1; n < NE_; n++)
                if (sc[n] > bv) { bv = sc[n]; best = n; }
            sidx = best;
        }
        __syncthreads();
        g_piror[b * C_ + tid] = embed[sidx * C_ + tid];
        __syncthreads();
    }
}

// NCHW fp32 + piror -> {skip NHWC fp32, packed fp16 hi/lo activations}
__global__ void input_prep(const float* __restrict__ x) {
    __shared__ float tile[32][33];
    int tx = threadIdx.x, ty = threadIdx.y;          // 32 x 8
    int by = blockIdx.x;                             // b*128 + y
    int b = by >> 7, y = by & 127;
    int x0 = blockIdx.y * 32, c0 = blockIdx.z * 32;
#pragma unroll
    for (int i = 0; i < 4; i++) {
        int cl = ty * 4 + i;
        tile[cl][tx] = x[((size_t)(b * C_ + c0 + cl) * HW_ + y) * HW_ + x0 + tx];
    }
    __syncthreads();
#pragma unroll
    for (int i = 0; i < 4; i++) {
        int xl = ty * 4 + i;
        int c = c0 + tx;
        float v = tile[tx][xl] + g_piror[b * C_ + c];
        size_t pix = (size_t)(b * HW_ + y) * HW_ + x0 + xl;
        g_skip[pix * 256 + c] = v;
        __half h = __float2half_rn(v);
        g_actA[pix * 512 + c] = h;
        g_actA[pix * 512 + 256 + c] = __float2half_rn(v - __half2float(h));
    }
}

// [i][oc][ic][ky][kx] fp32 -> fp16 [tap27][oc][ic], both stacks
__global__ void weight_prep(const float* __restrict__ w1, const float* __restrict__ w2) {
    int idx = blockIdx.x * 256 + threadIdx.x;        // < 27*256*256
    int ic = idx & 255, oc = (idx >> 8) & 255, t9 = idx >> 16;
    int i = t9 / 9, tap = t9 - 9 * i;
    size_t src = (((size_t)(i * C_ + oc) * C_ + ic) * 9) + tap;
    g_w1p[idx] = __float2half_rn(w1[src]);
    g_w2p[idx] = __float2half_rn(w2[src]);
}

__device__ __forceinline__ void store_pair_packed(__half* base, size_t pix, int oc,
                                                  float v0, float v1) {
    size_t o = pix * 512 + oc;
    __half h0 = __float2half_rn(v0), h1 = __float2half_rn(v1);
    *(__half2*)(base + o) = __halves2half2(h0, h1);
    __half l0 = __float2half_rn(v0 - __half2float(h0));
    __half l1 = __float2half_rn(v1 - __half2float(h1));
    *(__half2*)(base + o + 256) = __halves2half2(l0, l1);
}

// ---------------- conv3x3 on HMMA fp16 (2-pass split-activation precision) ----------------
// MODE 0: relu(conv(g_actA, w1)+b1) -> g_actB
// MODE 1: g_skip += conv(g_actB, w2)+b2; also -> g_actA
// MODE 2: like 1 but writes NCHW d_out
#define A_SUB   (130 * 128)              // one hi or lo sub-block (with 2 halo rows)
#define A_BYTES (2 * A_SUB)              // 33280
#define W_BYTES (384 * 128)              // 49152
#define STG     (A_BYTES + W_BYTES)      // 82432
#define SMEMSZ  (2 * STG)                // 164864

template <int MODE>
__global__ void __launch_bounds__(256, 1)
conv_hmma(const float* __restrict__ bias, float* __restrict__ dout, int widx) {
    extern __shared__ char sm[];
    const uint32_t sb = smem_u32(sm);
    const int tid = threadIdx.x, lane = tid & 31, wid = tid >> 5;
    const int y = blockIdx.x, ocb = blockIdx.y, b = blockIdx.z;

    const char* __restrict__ actb = (const char*)((MODE == 0) ? g_actA : g_actB);
    const char* __restrict__ wpb  = (const char*)((MODE == 0) ? g_w1p : g_w2p);

    // zero the x-halo rows (local rows 0 and 129 of hi and lo sub-blocks, both buffers)
    if (tid < 64) {
        int bufi = tid >> 5, sub = (tid >> 4) & 1, rr = (tid >> 3) & 1, seg = tid & 7;
        uint32_t addr = sb + bufi * STG + sub * A_SUB + (rr ? 129 : 0) * 128 + seg * 16;
        asm volatile("st.shared.v4.b32 [%0], {%1,%1,%1,%1};" :: "r"(addr), "r"(0) : "memory");
    }

    int kys[3];
    int nky = 0;
#pragma unroll
    for (int ky = 0; ky < 3; ky++) {
        int yin = y + ky - 1;
        if (yin >= 0 && yin < HW_) kys[nky++] = ky;
    }
    const int S = nky * 4;                           // 4 ic-chunks of 64 per ky

    auto load_stage = [&](int s, int buf) {
        int ky = kys[s >> 2], c = s & 3;
        int yin = y + ky - 1;
        const char* aSrc = actb + ((size_t)(b * HW_ + yin) * HW_) * 1024 + c * 128;
        uint32_t bb = sb + buf * STG;
        int t9 = widx * 9 + ky * 3;
#pragma unroll
        for (int j = 0; j < 20; j++) {
            int id = j * 256 + tid;
            if (id < 2048) {
                int half_ = id >> 10;                // 0 = hi, 1 = lo
                int px = (id >> 3) & 127, seg = id & 7;
                const char* src = aSrc + (size_t)px * 1024 + half_ * 512 + seg * 16;
                uint32_t dst = bb + half_ * A_SUB + (px + 1) * 128 +
                               ((seg * 16) ^ (((px + 1) & 7) << 4));
                cp16(dst, src);
            } else {
                int w = id - 2048;                   // < 3072
                int row = w >> 3, seg = w & 7;       // row = kx*128 + ocl
                int kx = row >> 7, ocl = row & 127;
                const char* src = wpb +
                    ((((size_t)(t9 + kx) * 256 + ocb * 128 + ocl) * 256) + c * 64) * 2 +
                    seg * 16;
                uint32_t dst = bb + A_BYTES + row * 128 + ((seg * 16) ^ ((row & 7) << 4));
                cp16(dst, src);
            }
        }
        asm volatile("cp.async.commit_group;" ::: "memory");
    };

    // per-warp fragment geometry (same as R5)
    const int m0 = (wid >> 1) * 32;          // px tile base
    const int wn = (wid & 1) * 64;           // oc tile base (local to 128)
    const int aRow0 = m0 + (lane & 15);
    const int aCol = (lane >> 4) * 16;       // bytes
    const int wRowL = wn + ((lane >> 4) << 3) + (lane & 7);
    const int wKsel = ((lane >> 3) & 1) * 16;
    const uint32_t wSw = (uint32_t)((lane & 7) << 4);

    float acc[2][8][4];
#pragma unroll
    for (int mt = 0; mt < 2; mt++)
#pragma unroll
        for (int g = 0; g < 8; g++)
#pragma unroll
            for (int k = 0; k < 4; k++) acc[mt][g][k] = 0.f;

    auto mma_stage = [&](uint32_t base) {
        uint32_t aB = base, wB = base + A_BYTES;
#pragma unroll
        for (int kx = 0; kx < 3; kx++) {
            int prow = aRow0 + kx;
            uint32_t aSw = (uint32_t)((prow & 7) << 4);
            uint32_t aHRow = aB + prow * 128;
            uint32_t aLRow = aB + A_SUB + prow * 128;
            uint32_t wRowAddr = wB + (kx * 128 + wRowL) * 128;
#pragma unroll
            for (int kh = 0; kh < 4; kh++) {
                int k0b = kh * 32;                   // bytes: 16 ic per k-step
                uint32_t ah[2][4], al[2][4], bw[4][4];
                uint32_t aH = aHRow + (uint32_t)((k0b + aCol) ^ aSw);
                ldsm4(ah[0], aH);
                ldsm4(ah[1], aH + 16 * 128);
                uint32_t aL = aLRow + (uint32_t)((k0b + aCol) ^ aSw);
                ldsm4(al[0], aL);
                ldsm4(al[1], aL + 16 * 128);
                uint32_t wAddr = wRowAddr + (uint32_t)((k0b + wKsel) ^ wSw);
#pragma unroll
                for (int bt = 0; bt < 4; bt++) ldsm4(bw[bt], wAddr + bt * 16 * 128);
#pragma unroll
                for (int mt = 0; mt < 2; mt++)
#pragma unroll
                    for (int g = 0; g < 8; g++)
                        mma16816(acc[mt][g], ah[mt], bw[g >> 1][(g & 1) * 2],
                                 bw[g >> 1][(g & 1) * 2 + 1]);
#pragma unroll
                for (int mt = 0; mt < 2; mt++)
#pragma unroll
                    for (int g = 0; g < 8; g++)
                        mma16816(acc[mt][g], al[mt], bw[g >> 1][(g & 1) * 2],
                                 bw[g >> 1][(g & 1) * 2 + 1]);
            }
        }
    };

    load_stage(0, 0);
#pragma unroll 1
    for (int s = 0; s < S; s++) {
        if (s + 1 < S) {
            load_stage(s + 1, (s + 1) & 1);
            asm volatile("cp.async.wait_group 1;" ::: "memory");
        } else {
            asm volatile("cp.async.wait_group 0;" ::: "memory");
        }
        __syncthreads();
        mma_stage(sb + (uint32_t)(s & 1) * STG);
        __syncthreads();
    }

    // ---- epilogue ----
    const int r = lane >> 2, q = lane & 3;
    const int ocbase = ocb * 128 + wn;
    const size_t pixBase = (size_t)(b * HW_ + y) * HW_;
#pragma unroll
    for (int mt = 0; mt < 2; mt++) {
        int px0 = m0 + mt * 16 + r;
#pragma unroll
        for (int g = 0; g < 8; g++) {
            int oc = ocbase + g * 8 + 2 * q;
            float bz0 = __ldg(&bias[oc]), bz1 = __ldg(&bias[oc + 1]);
#pragma unroll
            for (int hh = 0; hh < 2; hh++) {
                int px = px0 + hh * 8;
                float v0 = acc[mt][g][hh * 2 + 0] + bz0;
                float v1 = acc[mt][g][hh * 2 + 1] + bz1;
                size_t pix = pixBase + px;
                if (MODE == 0) {
                    v0 = fmaxf(v0, 0.f);
                    v1 = fmaxf(v1, 0.f);
                    store_pair_packed(g_actB, pix, oc, v0, v1);
                } else {
                    float2 sk = *(const float2*)&g_skip[pix * 256 + oc];
                    v0 += sk.x;
                    v1 += sk.y;
                    if (MODE == 1) {
                        *(float2*)&g_skip[pix * 256 + oc] = make_float2(v0, v1);
                        store_pair_packed(g_actA, pix, oc, v0, v1);
                    } else {
                        dout[((size_t)(b * C_ + oc) * HW_ + y) * HW_ + px] = v0;
                        dout[((size_t)(b * C_ + oc + 1) * HW_ + y) * HW_ + px] = v1;
                    }
                }
            }
        }
    }
}

// ---------------- launcher ----------------
extern "C" void kernel_launch(void* const* d_in, const int* in_sizes, int n_in,
                              void* d_out, int out_size) {
    const float* x        = (const float*)d_in[0];
    const float* gumbel_u = (const float*)d_in[1];
    const float* W_map    = (const float*)d_in[2];
    const float* proj_w   = (const float*)d_in[3];
    const float* proj_b   = (const float*)d_in[4];
    const float* embed    = (const float*)d_in[5];
    const float* res_w1   = (const float*)d_in[6];
    const float* res_b1   = (const float*)d_in[7];
    const float* res_w2   = (const float*)d_in[8];
    const float* res_b2   = (const float*)d_in[9];
    float* out = (float*)d_out;

    cudaFuncSetAttribute(conv_hmma<0>, cudaFuncAttributeMaxDynamicSharedMemorySize, SMEMSZ);
    cudaFuncSetAttribute(conv_hmma<1>, cudaFuncAttributeMaxDynamicSharedMemorySize, SMEMSZ);
    cudaFuncSetAttribute(conv_hmma<2>, cudaFuncAttributeMaxDynamicSharedMemorySize, SMEMSZ);

    pool_kernel<<<B_ * C_, 256>>>(x);
    piror_kernel<<<1, 256>>>(W_map, proj_w, proj_b, embed, gumbel_u);
    input_prep<<<dim3(B_ * HW_, 4, 8), dim3(32, 8)>>>(x);
    weight_prep<<<(27 * 256 * 256) / 256, 256>>>(res_w1, res_w2);

    dim3 cg(HW_, 2, B_);
    for (int i = 0; i < 3; i++) {
        conv_hmma<0><<<cg, 256, SMEMSZ>>>(res_b1 + i * C_, nullptr, i);
        if (i < 2)
            conv_hmma<1><<<cg, 256, SMEMSZ>>>(res_b2 + i * C_, nullptr, i);
        else
            conv_hmma<2><<<cg, 256, SMEMSZ>>>(res_b2 + i * C_, out, i);
    }
}

// round 9
// speedup vs baseline: 6.1116x; 1.5522x over previous
#include <cuda_runtime.h>
#include <cuda_fp16.h>
#include <cstdint>

#define B_  8
#define C_  256
#define HW_ 128
#define NE_ 20

// ---------------- device-global scratch (sanctioned; no runtime allocs) ----------------
__device__ float g_pooled[B_ * C_];
__device__ float g_piror[B_ * C_];
__device__ __align__(1024) float g_skip[(size_t)B_ * HW_ * HW_ * C_];   // NHWC fp32
// packed activations fp16: per pixel 256 halves (NHWC)
__device__ __align__(1024) __half g_actA[(size_t)B_ * HW_ * HW_ * 256];
__device__ __align__(1024) __half g_actB[(size_t)B_ * HW_ * HW_ * 256];
// packed weights fp16: [i*9+ky*3+kx][oc 256][ic 256]
__device__ __align__(1024) __half g_w1p[(size_t)27 * 256 * 256];
__device__ __align__(1024) __half g_w2p[(size_t)27 * 256 * 256];

// ---------------- PTX helpers ----------------
__device__ __forceinline__ uint32_t smem_u32(const void* p) {
    uint32_t a;
    asm("{ .reg .u64 t; cvta.to.shared.u64 t, %1; cvt.u32.u64 %0, t; }" : "=r"(a) : "l"(p));
    return a;
}
__device__ __forceinline__ void cp16(uint32_t dst, const void* src) {
    asm volatile("cp.async.cg.shared.global [%0], [%1], 16;" :: "r"(dst), "l"(src));
}
__device__ __forceinline__ void ldsm4(uint32_t* r, uint32_t a) {
    asm volatile("ldmatrix.sync.aligned.m8n8.x4.shared.b16 {%0,%1,%2,%3}, [%4];"
                 : "=r"(r[0]), "=r"(r[1]), "=r"(r[2]), "=r"(r[3]) : "r"(a));
}
__device__ __forceinline__ void mma16816(float* c, const uint32_t* a, uint32_t b0, uint32_t b1) {
    asm volatile(
        "mma.sync.aligned.m16n8k16.row.col.f32.f16.f16.f32 "
        "{%0,%1,%2,%3}, {%4,%5,%6,%7}, {%8,%9}, {%0,%1,%2,%3};"
        : "+f"(c[0]), "+f"(c[1]), "+f"(c[2]), "+f"(c[3])
        : "r"(a[0]), "r"(a[1]), "r"(a[2]), "r"(a[3]), "r"(b0), "r"(b1));
}

// ---------------- small kernels ----------------
__global__ void pool_kernel(const float* __restrict__ x) {
    int bc = blockIdx.x;
    const float* p = x + (size_t)bc * (HW_ * HW_);
    float s = 0.f;
    for (int i = threadIdx.x; i < HW_ * HW_; i += 256) s += p[i];
    __shared__ float red[256];
    red[threadIdx.x] = s;
    __syncthreads();
    for (int o = 128; o > 0; o >>= 1) {
        if (threadIdx.x < o) red[threadIdx.x] += red[threadIdx.x + o];
        __syncthreads();
    }
    if (threadIdx.x == 0) g_pooled[bc] = red[0] * (1.0f / (HW_ * HW_));
}

__global__ void piror_kernel(const float* __restrict__ Wmap,
                             const float* __restrict__ proj_w,
                             const float* __restrict__ proj_b,
                             const float* __restrict__ embed,
                             const float* __restrict__ gumbel_u) {
    __shared__ float m[C_];
    __shared__ float sc[NE_];
    __shared__ int sidx;
    int tid = threadIdx.x;
    for (int b = 0; b < B_; b++) {
        float acc = 0.f;
        for (int c = 0; c < C_; c++)
            acc += Wmap[tid * C_ + c] * g_pooled[b * C_ + c];
        m[tid] = 1.0f / (1.0f + expf(-acc));
        __syncthreads();
        if (tid < NE_) {
            float l = proj_b[tid];
            for (int c = 0; c < C_; c++) l += proj_w[tid * C_ + c] * m[c];
            float u = gumbel_u[b * NE_ + tid];
            float g = -logf(-logf(u + 1e-10f) + 1e-10f);
            sc[tid] = l + g;
        }
        __syncthreads();
        if (tid == 0) {
            int best = 0;
            float bv = sc[0];
            for (int n = 1; n < NE_; n++)
                if (sc[n] > bv) { bv = sc[n]; best = n; }
            sidx = best;
        }
        __syncthreads();
        g_piror[b * C_ + tid] = embed[sidx * C_ + tid];
        __syncthreads();
    }
}

// NCHW fp32 + piror -> {skip NHWC fp32, packed fp16 activations}
__global__ void input_prep(const float* __restrict__ x) {
    __shared__ float tile[32][33];
    int tx = threadIdx.x, ty = threadIdx.y;          // 32 x 8
    int by = blockIdx.x;                             // b*128 + y
    int b = by >> 7, y = by & 127;
    int x0 = blockIdx.y * 32, c0 = blockIdx.z * 32;
#pragma unroll
    for (int i = 0; i < 4; i++) {
        int cl = ty * 4 + i;
        tile[cl][tx] = x[((size_t)(b * C_ + c0 + cl) * HW_ + y) * HW_ + x0 + tx];
    }
    __syncthreads();
#pragma unroll
    for (int i = 0; i < 4; i++) {
        int xl = ty * 4 + i;
        int c = c0 + tx;
        float v = tile[tx][xl] + g_piror[b * C_ + c];
        size_t pix = (size_t)(b * HW_ + y) * HW_ + x0 + xl;
        g_skip[pix * 256 + c] = v;
        g_actA[pix * 256 + c] = __float2half_rn(v);
    }
}

// [i][oc][ic][ky][kx] fp32 -> fp16 [tap27][oc][ic], both stacks
__global__ void weight_prep(const float* __restrict__ w1, const float* __restrict__ w2) {
    int idx = blockIdx.x * 256 + threadIdx.x;        // < 27*256*256
    int ic = idx & 255, oc = (idx >> 8) & 255, t9 = idx >> 16;
    int i = t9 / 9, tap = t9 - 9 * i;
    size_t src = (((size_t)(i * C_ + oc) * C_ + ic) * 9) + tap;
    g_w1p[idx] = __float2half_rn(w1[src]);
    g_w2p[idx] = __float2half_rn(w2[src]);
}

// ---------------- conv3x3 on HMMA fp16 (single-pass, 3-deep cp.async ring) ----------------
// MODE 0: relu(conv(g_actA, w1)+b1) -> g_actB
// MODE 1: g_skip += conv(g_actB, w2)+b2; also -> g_actA
// MODE 2: like 1 but writes NCHW d_out
#define A_BYTES (130 * 128)              // 128 px + 2 halo rows, 64 ic x 2B
#define W_BYTES (384 * 128)              // 3 kx x 128 oc rows, 64 ic x 2B
#define STG     (A_BYTES + W_BYTES)      // 65792
#define NBUF    3
#define SMEMSZ  (NBUF * STG)             // 197376

template <int MODE>
__global__ void __launch_bounds__(256, 1)
conv_hmma(const float* __restrict__ bias, float* __restrict__ dout, int widx) {
    extern __shared__ char sm[];
    const uint32_t sb = smem_u32(sm);
    const int tid = threadIdx.x, lane = tid & 31, wid = tid >> 5;
    const int y = blockIdx.x, ocb = blockIdx.y, b = blockIdx.z;

    const char* __restrict__ actb = (const char*)((MODE == 0) ? g_actA : g_actB);
    const char* __restrict__ wpb  = (const char*)((MODE == 0) ? g_w1p : g_w2p);

    // zero the x-halo rows (local rows 0 and 129) of all 3 buffers; never overwritten
    if (tid < 48) {
        int bufi = tid >> 4, rr = (tid >> 3) & 1, seg = tid & 7;
        uint32_t addr = sb + bufi * STG + (rr ? 129 : 0) * 128 + seg * 16;
        asm volatile("st.shared.v4.b32 [%0], {%1,%1,%1,%1};" :: "r"(addr), "r"(0) : "memory");
    }

    int kys[3];
    int nky = 0;
#pragma unroll
    for (int ky = 0; ky < 3; ky++) {
        int yin = y + ky - 1;
        if (yin >= 0 && yin < HW_) kys[nky++] = ky;
    }
    const int S = nky * 4;                           // 4 ic-chunks of 64 per ky row

    auto load_stage = [&](int s, int buf) {
        int ky = kys[s >> 2], c = s & 3;
        int yin = y + ky - 1;
        const char* aSrc = actb + ((size_t)(b * HW_ + yin) * HW_) * 512 + c * 128;
        uint32_t bb = sb + buf * STG;
        int t9 = widx * 9 + ky * 3;
#pragma unroll
        for (int j = 0; j < 16; j++) {
            int id = j * 256 + tid;
            if (id < 1024) {
                int px = id >> 3, seg = id & 7;
                const char* src = aSrc + (size_t)px * 512 + seg * 16;
                uint32_t dst = bb + (px + 1) * 128 +
                               ((seg * 16) ^ (((px + 1) & 7) << 4));
                cp16(dst, src);
            } else {
                int w = id - 1024;                   // < 3072
                int row = w >> 3, seg = w & 7;       // row = kx*128 + ocl
                int kx = row >> 7, ocl = row & 127;
                const char* src = wpb +
                    ((((size_t)(t9 + kx) * 256 + ocb * 128 + ocl) * 256) + c * 64) * 2 +
                    seg * 16;
                uint32_t dst = bb + A_BYTES + row * 128 + ((seg * 16) ^ ((row & 7) << 4));
                cp16(dst, src);
            }
        }
        asm volatile("cp.async.commit_group;" ::: "memory");
    };

    // per-warp fragment geometry
    const int m0 = (wid >> 1) * 32;          // px tile base
    const int wn = (wid & 1) * 64;           // oc tile base (local to 128)
    const int aRow0 = m0 + (lane & 15);
    const int aCol = (lane >> 4) * 16;       // bytes
    const int wRowL = wn + ((lane >> 4) << 3) + (lane & 7);
    const int wKsel = ((lane >> 3) & 1) * 16;
    const uint32_t wSw = (uint32_t)((lane & 7) << 4);

    float acc[2][8][4];
#pragma unroll
    for (int mt = 0; mt < 2; mt++)
#pragma unroll
        for (int g = 0; g < 8; g++)
#pragma unroll
            for (int k = 0; k < 4; k++) acc[mt][g][k] = 0.f;

    auto mma_stage = [&](uint32_t base) {
        uint32_t aB = base, wB = base + A_BYTES;
#pragma unroll
        for (int kx = 0; kx < 3; kx++) {
            int prow = aRow0 + kx;
            uint32_t aSw = (uint32_t)((prow & 7) << 4);
            uint32_t aRowAddr = aB + prow * 128;
            uint32_t wRowAddr = wB + (kx * 128 + wRowL) * 128;
#pragma unroll
            for (int kh = 0; kh < 4; kh++) {
                int k0b = kh * 32;                   // 16 ic per k-step
                uint32_t ah[2][4], bw[4][4];
                uint32_t aH = aRowAddr + (uint32_t)((k0b + aCol) ^ aSw);
                ldsm4(ah[0], aH);
                ldsm4(ah[1], aH + 16 * 128);
                uint32_t wAddr = wRowAddr + (uint32_t)((k0b + wKsel) ^ wSw);
#pragma unroll
                for (int bt = 0; bt < 4; bt++) ldsm4(bw[bt], wAddr + bt * 16 * 128);
#pragma unroll
                for (int mt = 0; mt < 2; mt++)
#pragma unroll
                    for (int g = 0; g < 8; g++)
                        mma16816(acc[mt][g], ah[mt], bw[g >> 1][(g & 1) * 2],
                                 bw[g >> 1][(g & 1) * 2 + 1]);
            }
        }
    };

    load_stage(0, 0);
    if (S > 1) load_stage(1, 1);
#pragma unroll 1
    for (int s = 0; s < S; s++) {
        __syncthreads();                     // prior stage fully consumed before ring reuse
        if (s + 2 < S) {
            load_stage(s + 2, (s + 2) % NBUF);
            asm volatile("cp.async.wait_group 2;" ::: "memory");
        } else if (s + 1 < S) {
            asm volatile("cp.async.wait_group 1;" ::: "memory");
        } else {
            asm volatile("cp.async.wait_group 0;" ::: "memory");
        }
        __syncthreads();
        mma_stage(sb + (uint32_t)(s % NBUF) * STG);
    }

    // ---- epilogue ----
    const int r = lane >> 2, q = lane & 3;
    const int ocbase = ocb * 128 + wn;
    const size_t pixBase = (size_t)(b * HW_ + y) * HW_;
#pragma unroll
    for (int mt = 0; mt < 2; mt++) {
        int px0 = m0 + mt * 16 + r;
#pragma unroll
        for (int g = 0; g < 8; g++) {
            int oc = ocbase + g * 8 + 2 * q;
            float bz0 = __ldg(&bias[oc]), bz1 = __ldg(&bias[oc + 1]);
#pragma unroll
            for (int hh = 0; hh < 2; hh++) {
                int px = px0 + hh * 8;
                float v0 = acc[mt][g][hh * 2 + 0] + bz0;
                float v1 = acc[mt][g][hh * 2 + 1] + bz1;
                size_t pix = pixBase + px;
                if (MODE == 0) {
                    v0 = fmaxf(v0, 0.f);
                    v1 = fmaxf(v1, 0.f);
                    *(__half2*)&g_actB[pix * 256 + oc] =
                        __halves2half2(__float2half_rn(v0), __float2half_rn(v1));
                } else {
                    float2 sk = *(const float2*)&g_skip[pix * 256 + oc];
                    v0 += sk.x;
                    v1 += sk.y;
                    if (MODE == 1) {
                        *(float2*)&g_skip[pix * 256 + oc] = make_float2(v0, v1);
                        *(__half2*)&g_actA[pix * 256 + oc] =
                            __halves2half2(__float2half_rn(v0), __float2half_rn(v1));
                    } else {
                        dout[((size_t)(b * C_ + oc) * HW_ + y) * HW_ + px] = v0;
                        dout[((size_t)(b * C_ + oc + 1) * HW_ + y) * HW_ + px] = v1;
                    }
                }
            }
        }
    }
}

// ---------------- launcher ----------------
extern "C" void kernel_launch(void* const* d_in, const int* in_sizes, int n_in,
                              void* d_out, int out_size) {
    const float* x        = (const float*)d_in[0];
    const float* gumbel_u = (const float*)d_in[1];
    const float* W_map    = (const float*)d_in[2];
    const float* proj_w   = (const float*)d_in[3];
    const float* proj_b   = (const float*)d_in[4];
    const float* embed    = (const float*)d_in[5];
    const float* res_w1   = (const float*)d_in[6];
    const float* res_b1   = (const float*)d_in[7];
    const float* res_w2   = (const float*)d_in[8];
    const float* res_b2   = (const float*)d_in[9];
    float* out = (float*)d_out;

    cudaFuncSetAttribute(conv_hmma<0>, cudaFuncAttributeMaxDynamicSharedMemorySize, SMEMSZ);
    cudaFuncSetAttribute(conv_hmma<1>, cudaFuncAttributeMaxDynamicSharedMemorySize, SMEMSZ);
    cudaFuncSetAttribute(conv_hmma<2>, cudaFuncAttributeMaxDynamicSharedMemorySize, SMEMSZ);

    pool_kernel<<<B_ * C_, 256>>>(x);
    piror_kernel<<<1, 256>>>(W_map, proj_w, proj_b, embed, gumbel_u);
    input_prep<<<dim3(B_ * HW_, 4, 8), dim3(32, 8)>>>(x);
    weight_prep<<<(27 * 256 * 256) / 256, 256>>>(res_w1, res_w2);

    dim3 cg(HW_, 2, B_);
    for (int i = 0; i < 3; i++) {
        conv_hmma<0><<<cg, 256, SMEMSZ>>>(res_b1 + i * C_, nullptr, i);
        if (i < 2)
            conv_hmma<1><<<cg, 256, SMEMSZ>>>(res_b2 + i * C_, nullptr, i);
        else
            conv_hmma<2><<<cg, 256, SMEMSZ>>>(res_b2 + i * C_, out, i);
    }
}

// round 10
// speedup vs baseline: 6.6755x; 1.0923x over previous
#include <cuda_runtime.h>
#include <cuda_fp16.h>
#include <cstdint>

#define B_  8
#define C_  256
#define HW_ 128
#define NE_ 20

// ---------------- device-global scratch (sanctioned; no runtime allocs) ----------------
__device__ float g_pooled[B_ * C_];
__device__ float g_piror[B_ * C_];
__device__ __align__(1024) float g_skip[(size_t)B_ * HW_ * HW_ * C_];   // NHWC fp32
// packed activations fp16: per pixel 256 halves (NHWC)
__device__ __align__(1024) __half g_actA[(size_t)B_ * HW_ * HW_ * 256];
__device__ __align__(1024) __half g_actB[(size_t)B_ * HW_ * HW_ * 256];
// packed weights fp16: [i*9+ky*3+kx][oc 256][ic 256]
__device__ __align__(1024) __half g_w1p[(size_t)27 * 256 * 256];
__device__ __align__(1024) __half g_w2p[(size_t)27 * 256 * 256];

// ---------------- PTX helpers ----------------
__device__ __forceinline__ uint32_t smem_u32(const void* p) {
    uint32_t a;
    asm("{ .reg .u64 t; cvta.to.shared.u64 t, %1; cvt.u32.u64 %0, t; }" : "=r"(a) : "l"(p));
    return a;
}
__device__ __forceinline__ void cp16(uint32_t dst, const void* src) {
    asm volatile("cp.async.cg.shared.global [%0], [%1], 16;" :: "r"(dst), "l"(src));
}
// zero-fill variant: src_size = 0 -> 16 bytes of zeros
__device__ __forceinline__ void cp16z(uint32_t dst, const void* src, int sz) {
    asm volatile("cp.async.cg.shared.global [%0], [%1], 16, %2;"
                 :: "r"(dst), "l"(src), "r"(sz));
}
__device__ __forceinline__ void ldsm4(uint32_t* r, uint32_t a) {
    asm volatile("ldmatrix.sync.aligned.m8n8.x4.shared.b16 {%0,%1,%2,%3}, [%4];"
                 : "=r"(r[0]), "=r"(r[1]), "=r"(r[2]), "=r"(r[3]) : "r"(a));
}
__device__ __forceinline__ void mma16816(float* c, const uint32_t* a, uint32_t b0, uint32_t b1) {
    asm volatile(
        "mma.sync.aligned.m16n8k16.row.col.f32.f16.f16.f32 "
        "{%0,%1,%2,%3}, {%4,%5,%6,%7}, {%8,%9}, {%0,%1,%2,%3};"
        : "+f"(c[0]), "+f"(c[1]), "+f"(c[2]), "+f"(c[3])
        : "r"(a[0]), "r"(a[1]), "r"(a[2]), "r"(a[3]), "r"(b0), "r"(b1));
}

// ---------------- small kernels ----------------
__global__ void pool_kernel(const float* __restrict__ x) {
    int bc = blockIdx.x;
    const float* p = x + (size_t)bc * (HW_ * HW_);
    float s = 0.f;
    for (int i = threadIdx.x; i < HW_ * HW_; i += 256) s += p[i];
    __shared__ float red[256];
    red[threadIdx.x] = s;
    __syncthreads();
    for (int o = 128; o > 0; o >>= 1) {
        if (threadIdx.x < o) red[threadIdx.x] += red[threadIdx.x + o];
        __syncthreads();
    }
    if (threadIdx.x == 0) g_pooled[bc] = red[0] * (1.0f / (HW_ * HW_));
}

__global__ void piror_kernel(const float* __restrict__ Wmap,
                             const float* __restrict__ proj_w,
                             const float* __restrict__ proj_b,
                             const float* __restrict__ embed,
                             const float* __restrict__ gumbel_u) {
    __shared__ float m[C_];
    __shared__ float sc[NE_];
    __shared__ int sidx;
    int tid = threadIdx.x;
    for (int b = 0; b < B_; b++) {
        float acc = 0.f;
        for (int c = 0; c < C_; c++)
            acc += Wmap[tid * C_ + c] * g_pooled[b * C_ + c];
        m[tid] = 1.0f / (1.0f + expf(-acc));
        __syncthreads();
        if (tid < NE_) {
            float l = proj_b[tid];
            for (int c = 0; c < C_; c++) l += proj_w[tid * C_ + c] * m[c];
            float u = gumbel_u[b * NE_ + tid];
            float g = -logf(-logf(u + 1e-10f) + 1e-10f);
            sc[tid] = l + g;
        }
        __syncthreads();
        if (tid == 0) {
            int best = 0;
            float bv = sc[0];
            for (int n = 1; n < NE_; n++)
                if (sc[n] > bv) { bv = sc[n]; best = n; }
            sidx = best;
        }
        __syncthreads();
        g_piror[b * C_ + tid] = embed[sidx * C_ + tid];
        __syncthreads();
    }
}

// NCHW fp32 + piror -> {skip NHWC fp32, packed fp16 activations}
__global__ void input_prep(const float* __restrict__ x) {
    __shared__ float tile[32][33];
    int tx = threadIdx.x, ty = threadIdx.y;          // 32 x 8
    int by = blockIdx.x;                             // b*128 + y
    int b = by >> 7, y = by & 127;
    int x0 = blockIdx.y * 32, c0 = blockIdx.z * 32;
#pragma unroll
    for (int i = 0; i < 4; i++) {
        int cl = ty * 4 + i;
        tile[cl][tx] = x[((size_t)(b * C_ + c0 + cl) * HW_ + y) * HW_ + x0 + tx];
    }
    __syncthreads();
#pragma unroll
    for (int i = 0; i < 4; i++) {
        int xl = ty * 4 + i;
        int c = c0 + tx;
        float v = tile[tx][xl] + g_piror[b * C_ + c];
        size_t pix = (size_t)(b * HW_ + y) * HW_ + x0 + xl;
        g_skip[pix * 256 + c] = v;
        g_actA[pix * 256 + c] = __float2half_rn(v);
    }
}

// [i][oc][ic][ky][kx] fp32 -> fp16 [tap27][oc][ic], both stacks
__global__ void weight_prep(const float* __restrict__ w1, const float* __restrict__ w2) {
    int idx = blockIdx.x * 256 + threadIdx.x;        // < 27*256*256
    int ic = idx & 255, oc = (idx >> 8) & 255, t9 = idx >> 16;
    int i = t9 / 9, tap = t9 - 9 * i;
    size_t src = (((size_t)(i * C_ + oc) * C_ + ic) * 9) + tap;
    g_w1p[idx] = __float2half_rn(w1[src]);
    g_w2p[idx] = __float2half_rn(w2[src]);
}

// ---------------- conv3x3 on HMMA fp16: 2 rows per CTA (M=256), N=128 ----------------
// MODE 0: relu(conv(g_actA, w1)+b1) -> g_actB
// MODE 1: g_skip += conv(g_actB, w2)+b2; also -> g_actA
// MODE 2: like 1 but writes NCHW d_out
#define A_SUB   (130 * 128)              // one row sub-block (+2 halo rows), 64 ic x 2B
#define A_BYTES (2 * A_SUB)              // 33280 (two output-row input rows)
#define W_BYTES (384 * 128)              // 3 kx x 128 oc, 64 ic x 2B
#define STG     (A_BYTES + W_BYTES)      // 82432
#define SMEMSZ  (2 * STG)                // 164864

template <int MODE>
__global__ void __launch_bounds__(256, 1)
conv_hmma(const float* __restrict__ bias, float* __restrict__ dout, int widx) {
    extern __shared__ char sm[];
    const uint32_t sb = smem_u32(sm);
    const int tid = threadIdx.x, lane = tid & 31, wid = tid >> 5;
    const int y0 = blockIdx.x * 2, ocb = blockIdx.y, b = blockIdx.z;

    const char* __restrict__ actb = (const char*)((MODE == 0) ? g_actA : g_actB);
    const char* __restrict__ wpb  = (const char*)((MODE == 0) ? g_w1p : g_w2p);

    // zero x-halo rows (local rows 0,129) of both sub-blocks, both buffers
    if (tid < 64) {
        int bufi = tid >> 5, sub = (tid >> 4) & 1, rr = (tid >> 3) & 1, seg = tid & 7;
        uint32_t addr = sb + bufi * STG + sub * A_SUB + (rr ? 129 : 0) * 128 + seg * 16;
        asm volatile("st.shared.v4.b32 [%0], {%1,%1,%1,%1};" :: "r"(addr), "r"(0) : "memory");
    }

    const int S = 12;                                // 3 ky x 4 ic-chunks

    auto load_stage = [&](int s, int buf) {
        int ky = s >> 2, c = s & 3;
        int r0 = y0 + ky - 1;                        // input row for out row 0
        int r1 = y0 + ky;                            // input row for out row 1
        uint32_t bb = sb + buf * STG;
        int t9 = widx * 9 + ky * 3;
        const char* base = actb + ((size_t)b * HW_ * HW_) * 512 + c * 128;
#pragma unroll
        for (int j = 0; j < 20; j++) {
            int id = j * 256 + tid;
            if (id < 2048) {
                int rs = id >> 10;                   // 0 -> r0, 1 -> r1
                int px = (id >> 3) & 127, seg = id & 7;
                int row = rs ? r1 : r0;
                int ok = ((unsigned)row < HW_) ? 16 : 0;
                int rowc = (row < 0) ? 0 : ((row > 127) ? 127 : row);
                const char* src = base + ((size_t)rowc * HW_ + px) * 512 + seg * 16;
                uint32_t dst = bb + rs * A_SUB + (px + 1) * 128 +
                               ((seg * 16) ^ (((px + 1) & 7) << 4));
                cp16z(dst, src, ok);
            } else {
                int w = id - 2048;                   // < 3072
                int row = w >> 3, seg = w & 7;       // row = kx*128 + ocl
                int kx = row >> 7, ocl = row & 127;
                const char* src = (const char*)wpb +
                    ((((size_t)(t9 + kx) * 256 + ocb * 128 + ocl) * 256) + c * 64) * 2 +
                    seg * 16;
                uint32_t dst = bb + A_BYTES + row * 128 + ((seg * 16) ^ ((row & 7) << 4));
                cp16(dst, src);
            }
        }
        asm volatile("cp.async.commit_group;" ::: "memory");
    };

    // per-warp geometry: seg = wid>>1 (0..3): sub-row = seg>>1, px half = seg&1
    const int seg  = wid >> 1;
    const int sub  = seg >> 1;                       // which output row
    const int pxb  = (seg & 1) * 64;                 // px base within row
    const int wn   = (wid & 1) * 64;                 // oc base (local to 128)
    const int aRow0 = pxb + (lane & 15);
    const int aCol = (lane >> 4) * 16;               // bytes
    const int wRowL = wn + ((lane >> 4) << 3) + (lane & 7);
    const int wKsel = ((lane >> 3) & 1) * 16;
    const uint32_t wSw = (uint32_t)((lane & 7) << 4);

    float acc[4][8][4];
#pragma unroll
    for (int mt = 0; mt < 4; mt++)
#pragma unroll
        for (int g = 0; g < 8; g++)
#pragma unroll
            for (int k = 0; k < 4; k++) acc[mt][g][k] = 0.f;

    auto mma_stage = [&](uint32_t base) {
        uint32_t aB = base + sub * A_SUB, wB = base + A_BYTES;
#pragma unroll
        for (int kx = 0; kx < 3; kx++) {
            int prow = aRow0 + kx;
            uint32_t aSw = (uint32_t)((prow & 7) << 4);
            uint32_t aRowAddr = aB + prow * 128;
            uint32_t wRowAddr = wB + (kx * 128 + wRowL) * 128;
#pragma unroll
            for (int kh = 0; kh < 4; kh++) {
                int k0b = kh * 32;                   // 16 ic per k-step
                uint32_t ah[4][4], bw[4][4];
                uint32_t aH = aRowAddr + (uint32_t)((k0b + aCol) ^ aSw);
#pragma unroll
                for (int mt = 0; mt < 4; mt++) ldsm4(ah[mt], aH + mt * 16 * 128);
                uint32_t wAddr = wRowAddr + (uint32_t)((k0b + wKsel) ^ wSw);
#pragma unroll
                for (int bt = 0; bt < 4; bt++) ldsm4(bw[bt], wAddr + bt * 16 * 128);
#pragma unroll
                for (int mt = 0; mt < 4; mt++)
#pragma unroll
                    for (int g = 0; g < 8; g++)
                        mma16816(acc[mt][g], ah[mt], bw[g >> 1][(g & 1) * 2],
                                 bw[g >> 1][(g & 1) * 2 + 1]);
            }
        }
    };

    load_stage(0, 0);
    load_stage(1, 1);
#pragma unroll 1
    for (int s = 0; s < S; s++) {
        if (s + 1 < S) {
            asm volatile("cp.async.wait_group 1;" ::: "memory");
        } else {
            asm volatile("cp.async.wait_group 0;" ::: "memory");
        }
        __syncthreads();
        mma_stage(sb + (uint32_t)(s & 1) * STG);
        __syncthreads();                             // all consumed before ring reuse
        if (s + 2 < S) load_stage(s + 2, s & 1);
    }

    // ---- epilogue ----
    const int r = lane >> 2, q = lane & 3;
    const int ocbase = ocb * 128 + wn;
    const int yout = y0 + sub;
    const size_t pixBase = (size_t)(b * HW_ + yout) * HW_;
#pragma unroll
    for (int mt = 0; mt < 4; mt++) {
        int px0 = pxb + mt * 16 + r;
#pragma unroll
        for (int g = 0; g < 8; g++) {
            int oc = ocbase + g * 8 + 2 * q;
            float bz0 = __ldg(&bias[oc]), bz1 = __ldg(&bias[oc + 1]);
#pragma unroll
            for (int hh = 0; hh < 2; hh++) {
                int px = px0 + hh * 8;
                float v0 = acc[mt][g][hh * 2 + 0] + bz0;
                float v1 = acc[mt][g][hh * 2 + 1] + bz1;
                size_t pix = pixBase + px;
                if (MODE == 0) {
                    v0 = fmaxf(v0, 0.f);
                    v1 = fmaxf(v1, 0.f);
                    *(__half2*)&g_actB[pix * 256 + oc] =
                        __halves2half2(__float2half_rn(v0), __float2half_rn(v1));
                } else {
                    float2 sk = *(const float2*)&g_skip[pix * 256 + oc];
                    v0 += sk.x;
                    v1 += sk.y;
                    if (MODE == 1) {
                        *(float2*)&g_skip[pix * 256 + oc] = make_float2(v0, v1);
                        *(__half2*)&g_actA[pix * 256 + oc] =
                            __halves2half2(__float2half_rn(v0), __float2half_rn(v1));
                    } else {
                        dout[((size_t)(b * C_ + oc) * HW_ + yout) * HW_ + px] = v0;
                        dout[((size_t)(b * C_ + oc + 1) * HW_ + yout) * HW_ + px] = v1;
                    }
                }
            }
        }
    }
}

// ---------------- launcher ----------------
extern "C" void kernel_launch(void* const* d_in, const int* in_sizes, int n_in,
                              void* d_out, int out_size) {
    const float* x        = (const float*)d_in[0];
    const float* gumbel_u = (const float*)d_in[1];
    const float* W_map    = (const float*)d_in[2];
    const float* proj_w   = (const float*)d_in[3];
    const float* proj_b   = (const float*)d_in[4];
    const float* embed    = (const float*)d_in[5];
    const float* res_w1   = (const float*)d_in[6];
    const float* res_b1   = (const float*)d_in[7];
    const float* res_w2   = (const float*)d_in[8];
    const float* res_b2   = (const float*)d_in[9];
    float* out = (float*)d_out;

    cudaFuncSetAttribute(conv_hmma<0>, cudaFuncAttributeMaxDynamicSharedMemorySize, SMEMSZ);
    cudaFuncSetAttribute(conv_hmma<1>, cudaFuncAttributeMaxDynamicSharedMemorySize, SMEMSZ);
    cudaFuncSetAttribute(conv_hmma<2>, cudaFuncAttributeMaxDynamicSharedMemorySize, SMEMSZ);

    pool_kernel<<<B_ * C_, 256>>>(x);
    piror_kernel<<<1, 256>>>(W_map, proj_w, proj_b, embed, gumbel_u);
    input_prep<<<dim3(B_ * HW_, 4, 8), dim3(32, 8)>>>(x);
    weight_prep<<<(27 * 256 * 256) / 256, 256>>>(res_w1, res_w2);

    dim3 cg(HW_ / 2, 2, B_);
    for (int i = 0; i < 3; i++) {
        conv_hmma<0><<<cg, 256, SMEMSZ>>>(res_b1 + i * C_, nullptr, i);
        if (i < 2)
            conv_hmma<1><<<cg, 256, SMEMSZ>>>(res_b2 + i * C_, nullptr, i);
        else
            conv_hmma<2><<<cg, 256, SMEMSZ>>>(res_b2 + i * C_, out, i);
    }
}

// round 12
// speedup vs baseline: 6.8972x; 1.0332x over previous
#include <cuda_runtime.h>
#include <cuda_fp16.h>
#include <cstdint>

#define B_  8
#define C_  256
#define HW_ 128
#define NE_ 20

// ---------------- device-global scratch (sanctioned; no runtime allocs) ----------------
__device__ float g_pooled[B_ * C_];
__device__ float g_piror[B_ * C_];
__device__ __align__(1024) float g_skip[(size_t)B_ * HW_ * HW_ * C_];   // NHWC fp32
// packed activations fp16: per pixel 256 halves (NHWC)
__device__ __align__(1024) __half g_actA[(size_t)B_ * HW_ * HW_ * 256];
__device__ __align__(1024) __half g_actB[(size_t)B_ * HW_ * HW_ * 256];
// packed weights fp16: [i*9+ky*3+kx][oc 256][ic 256]
__device__ __align__(1024) __half g_w1p[(size_t)27 * 256 * 256];
__device__ __align__(1024) __half g_w2p[(size_t)27 * 256 * 256];

// ---------------- PTX helpers ----------------
__device__ __forceinline__ uint32_t smem_u32(const void* p) {
    uint32_t a;
    asm("{ .reg .u64 t; cvta.to.shared.u64 t, %1; cvt.u32.u64 %0, t; }" : "=r"(a) : "l"(p));
    return a;
}
__device__ __forceinline__ void cp16(uint32_t dst, const void* src) {
    asm volatile("cp.async.cg.shared.global [%0], [%1], 16;" :: "r"(dst), "l"(src));
}
// zero-fill variant: src_size = 0 -> 16 bytes of zeros
__device__ __forceinline__ void cp16z(uint32_t dst, const void* src, int sz) {
    asm volatile("cp.async.cg.shared.global [%0], [%1], 16, %2;"
                 :: "r"(dst), "l"(src), "r"(sz));
}
__device__ __forceinline__ void ldsm4(uint32_t* r, uint32_t a) {
    asm volatile("ldmatrix.sync.aligned.m8n8.x4.shared.b16 {%0,%1,%2,%3}, [%4];"
                 : "=r"(r[0]), "=r"(r[1]), "=r"(r[2]), "=r"(r[3]) : "r"(a));
}
__device__ __forceinline__ void mma16816(float* c, const uint32_t* a, uint32_t b0, uint32_t b1) {
    asm volatile(
        "mma.sync.aligned.m16n8k16.row.col.f32.f16.f16.f32 "
        "{%0,%1,%2,%3}, {%4,%5,%6,%7}, {%8,%9}, {%0,%1,%2,%3};"
        : "+f"(c[0]), "+f"(c[1]), "+f"(c[2]), "+f"(c[3])
        : "r"(a[0]), "r"(a[1]), "r"(a[2]), "r"(a[3]), "r"(b0), "r"(b1));
}

// ---------------- small kernels ----------------
__global__ void pool_kernel(const float* __restrict__ x) {
    int bc = blockIdx.x;
    const float* p = x + (size_t)bc * (HW_ * HW_);
    float s = 0.f;
    for (int i = threadIdx.x; i < HW_ * HW_; i += 256) s += p[i];
    __shared__ float red[256];
    red[threadIdx.x] = s;
    __syncthreads();
    for (int o = 128; o > 0; o >>= 1) {
        if (threadIdx.x < o) red[threadIdx.x] += red[threadIdx.x + o];
        __syncthreads();
    }
    if (threadIdx.x == 0) g_pooled[bc] = red[0] * (1.0f / (HW_ * HW_));
}

__global__ void piror_kernel(const float* __restrict__ Wmap,
                             const float* __restrict__ proj_w,
                             const float* __restrict__ proj_b,
                             const float* __restrict__ embed,
                             const float* __restrict__ gumbel_u) {
    __shared__ float m[C_];
    __shared__ float sc[NE_];
    __shared__ int sidx;
    int tid = threadIdx.x;
    for (int b = 0; b < B_; b++) {
        float acc = 0.f;
        for (int c = 0; c < C_; c++)
            acc += Wmap[tid * C_ + c] * g_pooled[b * C_ + c];
        m[tid] = 1.0f / (1.0f + expf(-acc));
        __syncthreads();
        if (tid < NE_) {
            float l = proj_b[tid];
            for (int c = 0; c < C_; c++) l += proj_w[tid * C_ + c] * m[c];
            float u = gumbel_u[b * NE_ + tid];
            float g = -logf(-logf(u + 1e-10f) + 1e-10f);
            sc[tid] = l + g;
        }
        __syncthreads();
        if (tid == 0) {
            int best = 0;
            float bv = sc[0];
            for (int n = 1; n < NE_; n++)
                if (sc[n] > bv) { bv = sc[n]; best = n; }
            sidx = best;
        }
        __syncthreads();
        g_piror[b * C_ + tid] = embed[sidx * C_ + tid];
        __syncthreads();
    }
}

// NCHW fp32 + piror -> {skip NHWC fp32, packed fp16 activations}
__global__ void input_prep(const float* __restrict__ x) {
    __shared__ float tile[32][33];
    int tx = threadIdx.x, ty = threadIdx.y;          // 32 x 8
    int by = blockIdx.x;                             // b*128 + y
    int b = by >> 7, y = by & 127;
    int x0 = blockIdx.y * 32, c0 = blockIdx.z * 32;
#pragma unroll
    for (int i = 0; i < 4; i++) {
        int cl = ty * 4 + i;
        tile[cl][tx] = x[((size_t)(b * C_ + c0 + cl) * HW_ + y) * HW_ + x0 + tx];
    }
    __syncthreads();
#pragma unroll
    for (int i = 0; i < 4; i++) {
        int xl = ty * 4 + i;
        int c = c0 + tx;
        float v = tile[tx][xl] + g_piror[b * C_ + c];
        size_t pix = (size_t)(b * HW_ + y) * HW_ + x0 + xl;
        g_skip[pix * 256 + c] = v;
        g_actA[pix * 256 + c] = __float2half_rn(v);
    }
}

// [i][oc][ic][ky][kx] fp32 -> fp16 [tap27][oc][ic], both stacks
__global__ void weight_prep(const float* __restrict__ w1, const float* __restrict__ w2) {
    int idx = blockIdx.x * 256 + threadIdx.x;        // < 27*256*256
    int ic = idx & 255, oc = (idx >> 8) & 255, t9 = idx >> 16;
    int i = t9 / 9, tap = t9 - 9 * i;
    size_t src = (((size_t)(i * C_ + oc) * C_ + ic) * 9) + tap;
    g_w1p[idx] = __float2half_rn(w1[src]);
    g_w2p[idx] = __float2half_rn(w2[src]);
}

// ---------------- conv3x3 on HMMA fp16: 2 rows per CTA (M=256), N=128, 512 thr ----------------
// MODE 0: relu(conv(g_actA, w1)+b1) -> g_actB
// MODE 1: g_skip += conv(g_actB, w2)+b2; also -> g_actA
// MODE 2: like 1 but writes NCHW d_out
#define A_SUB   (130 * 128)              // one row sub-block (+2 halo rows), 64 ic x 2B
#define A_BYTES (2 * A_SUB)              // 33280
#define W_BYTES (384 * 128)              // 3 kx x 128 oc, 64 ic x 2B
#define STG     (A_BYTES + W_BYTES)      // 82432
#define SMEMSZ  (2 * STG)                // 164864
#define NTHR    512

template <int MODE>
__global__ void __launch_bounds__(NTHR, 1)
conv_hmma(const float* __restrict__ bias, float* __restrict__ dout, int widx) {
    extern __shared__ char sm[];
    const uint32_t sb = smem_u32(sm);
    const int tid = threadIdx.x, lane = tid & 31, wid = tid >> 5;   // 16 warps
    const int y0 = blockIdx.x * 2, ocb = blockIdx.y, b = blockIdx.z;

    const char* __restrict__ actb = (const char*)((MODE == 0) ? g_actA : g_actB);
    const char* __restrict__ wpb  = (const char*)((MODE == 0) ? g_w1p : g_w2p);

    // zero x-halo rows (local rows 0,129) of both sub-blocks, both buffers
    if (tid < 64) {
        int bufi = tid >> 5, sub = (tid >> 4) & 1, rr = (tid >> 3) & 1, seg = tid & 7;
        uint32_t addr = sb + bufi * STG + sub * A_SUB + (rr ? 129 : 0) * 128 + seg * 16;
        asm volatile("st.shared.v4.b32 [%0], {%1,%1,%1,%1};" :: "r"(addr), "r"(0) : "memory");
    }

    const int S = 12;                                // 3 ky x 4 ic-chunks

    auto load_stage = [&](int s, int buf) {
        int ky = s >> 2, c = s & 3;
        int r0 = y0 + ky - 1;                        // input row for out row 0
        int r1 = y0 + ky;                            // input row for out row 1
        uint32_t bb = sb + buf * STG;
        int t9 = widx * 9 + ky * 3;
        const char* base = actb + ((size_t)b * HW_ * HW_) * 512 + c * 128;
#pragma unroll
        for (int j = 0; j < 10; j++) {
            int id = j * NTHR + tid;
            if (id < 2048) {
                int rs = id >> 10;                   // 0 -> r0, 1 -> r1
                int px = (id >> 3) & 127, seg = id & 7;
                int row = rs ? r1 : r0;
                int ok = ((unsigned)row < HW_) ? 16 : 0;
                int rowc = (row < 0) ? 0 : ((row > 127) ? 127 : row);
                const char* src = base + ((size_t)rowc * HW_ + px) * 512 + seg * 16;
                uint32_t dst = bb + rs * A_SUB + (px + 1) * 128 +
                               ((seg * 16) ^ (((px + 1) & 7) << 4));
                cp16z(dst, src, ok);
            } else {
                int w = id - 2048;                   // < 3072
                int row = w >> 3, seg = w & 7;       // row = kx*128 + ocl
                int kx = row >> 7, ocl = row & 127;
                const char* src = (const char*)wpb +
                    ((((size_t)(t9 + kx) * 256 + ocb * 128 + ocl) * 256) + c * 64) * 2 +
                    seg * 16;
                uint32_t dst = bb + A_BYTES + row * 128 + ((seg * 16) ^ ((row & 7) << 4));
                cp16(dst, src);
            }
        }
        asm volatile("cp.async.commit_group;" ::: "memory");
    };

    // per-warp geometry: nsl = wid & 1 (oc 64-half); msl = wid >> 1 (0..7):
    //   sub = msl >> 2 (output row), pxb = (msl & 3) * 32
    const int nsl = wid & 1;
    const int msl = wid >> 1;
    const int sub = msl >> 2;
    const int pxb = (msl & 3) * 32;
    const int wn  = nsl * 64;
    const int aRow0 = pxb + (lane & 15);
    const int aCol = (lane >> 4) * 16;               // bytes
    const int wRowL = wn + ((lane >> 4) << 3) + (lane & 7);
    const int wKsel = ((lane >> 3) & 1) * 16;
    const uint32_t wSw = (uint32_t)((lane & 7) << 4);

    float acc[2][8][4];
#pragma unroll
    for (int mt = 0; mt < 2; mt++)
#pragma unroll
        for (int g = 0; g < 8; g++)
#pragma unroll
            for (int k = 0; k < 4; k++) acc[mt][g][k] = 0.f;

    auto mma_stage = [&](uint32_t base) {
        uint32_t aB = base + sub * A_SUB, wB = base + A_BYTES;
#pragma unroll
        for (int kx = 0; kx < 3; kx++) {
            int prow = aRow0 + kx;
            uint32_t aSw = (uint32_t)((prow & 7) << 4);
            uint32_t aRowAddr = aB + prow * 128;
            uint32_t wRowAddr = wB + (kx * 128 + wRowL) * 128;
#pragma unroll
            for (int kh = 0; kh < 4; kh++) {
                int k0b = kh * 32;                   // 16 ic per k-step
                uint32_t ah[2][4], bw[4][4];
                uint32_t aH = aRowAddr + (uint32_t)((k0b + aCol) ^ aSw);
#pragma unroll
                for (int mt = 0; mt < 2; mt++) ldsm4(ah[mt], aH + mt * 16 * 128);
                uint32_t wAddr = wRowAddr + (uint32_t)((k0b + wKsel) ^ wSw);
#pragma unroll
                for (int bt = 0; bt < 4; bt++) ldsm4(bw[bt], wAddr + bt * 16 * 128);
#pragma unroll
                for (int mt = 0; mt < 2; mt++)
#pragma unroll
                    for (int g = 0; g < 8; g++)
                        mma16816(acc[mt][g], ah[mt], bw[g >> 1][(g & 1) * 2],
                                 bw[g >> 1][(g & 1) * 2 + 1]);
            }
        }
    };

    load_stage(0, 0);
    load_stage(1, 1);
#pragma unroll 1
    for (int s = 0; s < S; s++) {
        if (s + 1 < S) {
            asm volatile("cp.async.wait_group 1;" ::: "memory");
        } else {
            asm volatile("cp.async.wait_group 0;" ::: "memory");
        }
        __syncthreads();
        mma_stage(sb + (uint32_t)(s & 1) * STG);
        __syncthreads();                             // all consumed before ring reuse
        if (s + 2 < S) load_stage(s + 2, s & 1);
    }

    // ---- epilogue ----
    const int r = lane >> 2, q = lane & 3;
    const int ocbase = ocb * 128 + wn;
    const int yout = y0 + sub;
    const size_t pixBase = (size_t)(b * HW_ + yout) * HW_;
#pragma unroll
    for (int mt = 0; mt < 2; mt++) {
        int px0 = pxb + mt * 16 + r;
#pragma unroll
        for (int g = 0; g < 8; g++) {
            int oc = ocbase + g * 8 + 2 * q;
            float bz0 = __ldg(&bias[oc]), bz1 = __ldg(&bias[oc + 1]);
#pragma unroll
            for (int hh = 0; hh < 2; hh++) {
                int px = px0 + hh * 8;
                float v0 = acc[mt][g][hh * 2 + 0] + bz0;
                float v1 = acc[mt][g][hh * 2 + 1] + bz1;
                size_t pix = pixBase + px;
                if (MODE == 0) {
                    v0 = fmaxf(v0, 0.f);
                    v1 = fmaxf(v1, 0.f);
                    *(__half2*)&g_actB[pix * 256 + oc] =
                        __halves2half2(__float2half_rn(v0), __float2half_rn(v1));
                } else {
                    float2 sk = *(const float2*)&g_skip[pix * 256 + oc];
                    v0 += sk.x;
                    v1 += sk.y;
                    if (MODE == 1) {
                        *(float2*)&g_skip[pix * 256 + oc] = make_float2(v0, v1);
                        *(__half2*)&g_actA[pix * 256 + oc] =
                            __halves2half2(__float2half_rn(v0), __float2half_rn(v1));
                    } else {
                        dout[((size_t)(b * C_ + oc) * HW_ + yout) * HW_ + px] = v0;
                        dout[((size_t)(b * C_ + oc + 1) * HW_ + yout) * HW_ + px] = v1;
                    }
                }
            }
        }
    }
}

// ---------------- launcher ----------------
extern "C" void kernel_launch(void* const* d_in, const int* in_sizes, int n_in,
                              void* d_out, int out_size) {
    const float* x        = (const float*)d_in[0];
    const float* gumbel_u = (const float*)d_in[1];
    const float* W_map    = (const float*)d_in[2];
    const float* proj_w   = (const float*)d_in[3];
    const float* proj_b   = (const float*)d_in[4];
    const float* embed    = (const float*)d_in[5];
    const float* res_w1   = (const float*)d_in[6];
    const float* res_b1   = (const float*)d_in[7];
    const float* res_w2   = (const float*)d_in[8];
    const float* res_b2   = (const float*)d_in[9];
    float* out = (float*)d_out;

    cudaFuncSetAttribute(conv_hmma<0>, cudaFuncAttributeMaxDynamicSharedMemorySize, SMEMSZ);
    cudaFuncSetAttribute(conv_hmma<1>, cudaFuncAttributeMaxDynamicSharedMemorySize, SMEMSZ);
    cudaFuncSetAttribute(conv_hmma<2>, cudaFuncAttributeMaxDynamicSharedMemorySize, SMEMSZ);

    pool_kernel<<<B_ * C_, 256>>>(x);
    piror_kernel<<<1, 256>>>(W_map, proj_w, proj_b, embed, gumbel_u);
    input_prep<<<dim3(B_ * HW_, 4, 8), dim3(32, 8)>>>(x);
    weight_prep<<<(27 * 256 * 256) / 256, 256>>>(res_w1, res_w2);

    dim3 cg(HW_ / 2, 2, B_);
    for (int i = 0; i < 3; i++) {
        conv_hmma<0><<<cg, NTHR, SMEMSZ>>>(res_b1 + i * C_, nullptr, i);
        if (i < 2)
            conv_hmma<1><<<cg, NTHR, SMEMSZ>>>(res_b2 + i * C_, nullptr, i);
        else
            conv_hmma<2><<<cg, NTHR, SMEMSZ>>>(res_b2 + i * C_, out, i);
    }
}